// round 4
// baseline (speedup 1.0000x reference)
#include <cuda_runtime.h>
#include <cuda_bf16.h>
#include <cstdint>

// ---------------- problem constants ----------------
#define N_TOK 8192
#define H     1024
#define E     8
#define IE    512
#define F2    1024
#define VOCAB 32000

// ---------------- scratch ----------------
__device__ int g_expert_ids[N_TOK];
__device__ int g_counts[E];
__device__ int g_offsets[E + 1];
__device__ int g_sorted[N_TOK];
__device__ int g_tile_expert[96];
__device__ int g_tile_mstart[96];
__device__ int g_num_tiles;

__device__ __nv_bfloat16 g_xs_hi[(size_t)N_TOK * H];   // sorted order
__device__ __nv_bfloat16 g_xs_lo[(size_t)N_TOK * H];
__device__ __nv_bfloat16 g_gup_hi[(size_t)E * H * F2];
__device__ __nv_bfloat16 g_gup_lo[(size_t)E * H * F2];
__device__ __nv_bfloat16 g_dwn_hi[(size_t)E * IE * H];
__device__ __nv_bfloat16 g_dwn_lo[(size_t)E * IE * H];
__device__ __nv_bfloat16 g_inter_hi[(size_t)N_TOK * IE];
__device__ __nv_bfloat16 g_inter_lo[(size_t)N_TOK * IE];

// ---------------- PTX helpers ----------------
__device__ __forceinline__ uint32_t s2u(const void* p) {
    uint32_t a;
    asm("{ .reg .u64 t; cvta.to.shared.u64 t, %1; cvt.u32.u64 %0, t; }"
        : "=r"(a) : "l"(p));
    return a;
}
__device__ __forceinline__ void mbar_init(uint32_t a, uint32_t cnt) {
    asm volatile("mbarrier.init.shared.b64 [%0], %1;" :: "r"(a), "r"(cnt) : "memory");
}
__device__ __forceinline__ void mbar_expect(uint32_t a, uint32_t bytes) {
    asm volatile("mbarrier.arrive.expect_tx.shared.b64 _, [%0], %1;"
                 :: "r"(a), "r"(bytes) : "memory");
}
__device__ __forceinline__ void mbar_wait(uint32_t a, uint32_t parity) {
    uint32_t done;
    do {
        asm volatile(
            "{\n\t.reg .pred p;\n\t"
            "mbarrier.try_wait.parity.shared::cta.b64 p, [%1], %2;\n\t"
            "selp.b32 %0, 1, 0, p;\n\t}"
            : "=r"(done) : "r"(a), "r"(parity) : "memory");
    } while (!done);
}
__device__ __forceinline__ void bulk_g2s(uint32_t dst, const void* src,
                                         uint32_t bytes, uint32_t mbar) {
    asm volatile(
        "cp.async.bulk.shared::cluster.global.mbarrier::complete_tx::bytes "
        "[%0], [%1], %2, [%3];"
        :: "r"(dst), "l"(src), "r"(bytes), "r"(mbar) : "memory");
}
__device__ __forceinline__ void fence_async() {
    asm volatile("fence.proxy.async.shared::cta;" ::: "memory");
}
__device__ __forceinline__ void ldmx4(uint32_t* r, uint32_t a) {
    asm volatile("ldmatrix.sync.aligned.m8n8.x4.shared.b16 {%0,%1,%2,%3}, [%4];"
                 : "=r"(r[0]), "=r"(r[1]), "=r"(r[2]), "=r"(r[3]) : "r"(a));
}
__device__ __forceinline__ void ldmx4t(uint32_t* r, uint32_t a) {
    asm volatile("ldmatrix.sync.aligned.m8n8.x4.trans.shared.b16 {%0,%1,%2,%3}, [%4];"
                 : "=r"(r[0]), "=r"(r[1]), "=r"(r[2]), "=r"(r[3]) : "r"(a));
}
__device__ __forceinline__ void mma16816(float* d, const uint32_t* a,
                                         const uint32_t* b) {
    asm volatile(
        "mma.sync.aligned.m16n8k16.row.col.f32.bf16.bf16.f32 "
        "{%0,%1,%2,%3}, {%4,%5,%6,%7}, {%8,%9}, {%0,%1,%2,%3};"
        : "+f"(d[0]), "+f"(d[1]), "+f"(d[2]), "+f"(d[3])
        : "r"(a[0]), "r"(a[1]), "r"(a[2]), "r"(a[3]), "r"(b[0]), "r"(b[1]));
}

// ---------------- smem layout ----------------
#define BK     64
#define A_ROWB 144   // 64 bf16 data (128B) + 16B pad
#define B_ROWB 272   // 128 bf16 data (256B) + 16B pad
#define OFF_AH 0
#define OFF_AL 18432
#define OFF_BH 36864
#define OFF_BL 54272
#define STG    71680
#define STAGE_BASE 1024
#define SMEM_TOT (STAGE_BASE + 3 * STG)   // 216064
#define STAGE_BYTES 65536u

__device__ __forceinline__ uint32_t a_addr(uint32_t base, int lane, int mbase,
                                           int k16) {
    int row = mbase + (lane & 15);
    return base + row * A_ROWB + k16 * 32 + ((lane >> 4) << 4);
}
__device__ __forceinline__ uint32_t b_addr(uint32_t base, int lane, int nbase,
                                           int k16) {
    int krow = k16 * 16 + (lane & 15);
    return base + krow * B_ROWB + nbase * 2 + ((lane >> 4) << 4);
}

// one k16 step: 12 ldmatrix.x4, 48 HMMA per warp
__device__ __forceinline__ void compute_k16(uint32_t stg, int lane, int warpM,
                                            int p0, int p1, int k16,
                                            float acc[4][4][4]) {
    uint32_t ah[4][4], al[4][4], bh[2][4], bl[2][4];
#pragma unroll
    for (int i = 0; i < 4; i++) {
        ldmx4(ah[i], a_addr(stg + OFF_AH, lane, warpM * 64 + i * 16, k16));
        ldmx4(al[i], a_addr(stg + OFF_AL, lane, warpM * 64 + i * 16, k16));
    }
    ldmx4t(bh[0], b_addr(stg + OFF_BH, lane, p0, k16));
    ldmx4t(bh[1], b_addr(stg + OFF_BH, lane, p1, k16));
    ldmx4t(bl[0], b_addr(stg + OFF_BL, lane, p0, k16));
    ldmx4t(bl[1], b_addr(stg + OFF_BL, lane, p1, k16));
#pragma unroll
    for (int i = 0; i < 4; i++) {
#pragma unroll
        for (int j = 0; j < 4; j++) {
            const uint32_t* bhp = &bh[j >> 1][(j & 1) * 2];
            const uint32_t* blp = &bl[j >> 1][(j & 1) * 2];
            mma16816(acc[i][j], ah[i], bhp);
            mma16816(acc[i][j], ah[i], blp);
            mma16816(acc[i][j], al[i], bhp);
        }
    }
}

// ---------------- small kernels ----------------
__global__ void k_init() {
    if (threadIdx.x < E) g_counts[threadIdx.x] = 0;
}

__global__ void k_router(const float* __restrict__ mu, const int* __restrict__ tok,
                         const float* __restrict__ w) {
    __shared__ float ws[E * H];
    int tid = threadIdx.x;
    for (int i = tid; i < E * H; i += 256) ws[i] = w[i];
    __syncthreads();
    int warp = tid >> 5, lane = tid & 31;
    int n = blockIdx.x * 8 + warp;
    const float* mrow = mu + (size_t)n * H;
    float acc[E];
#pragma unroll
    for (int e = 0; e < E; e++) acc[e] = 0.f;
    for (int h = lane; h < H; h += 32) {
        float m = mrow[h];
#pragma unroll
        for (int e = 0; e < E; e++) acc[e] += m * ws[e * H + h];
    }
#pragma unroll
    for (int off = 16; off > 0; off >>= 1)
#pragma unroll
        for (int e = 0; e < E; e++)
            acc[e] += __shfl_down_sync(0xffffffffu, acc[e], off);
    if (lane == 0) {
        int id = tok[n];
        if (id < 0) id = 0;
        if (id >= VOCAB) id = VOCAB - 1;
        int base = id & (E - 1);
        float best = -1e30f;
        int be = 0;
#pragma unroll
        for (int e = 0; e < E; e++) {
            float v = acc[e] + (e == base ? 10.0f : 0.0f);
            if (v > best) { best = v; be = e; }
        }
        g_expert_ids[n] = be;
        atomicAdd(&g_counts[be], 1);
    }
}

__global__ void k_plan_scatter() {
    __shared__ int scur[E];
    if (threadIdx.x == 0) {
        int off = 0;
        for (int e = 0; e < E; e++) {
            g_offsets[e] = off;
            scur[e] = off;
            off += g_counts[e];
        }
        g_offsets[E] = off;
        int tt = 0;
        for (int e = 0; e < E; e++) {
            int cnt = g_counts[e];
            for (int ms = 0; ms < cnt; ms += 128) {
                g_tile_expert[tt] = e;
                g_tile_mstart[tt] = ms;
                tt++;
            }
        }
        g_num_tiles = tt;
    }
    __syncthreads();
    for (int n = threadIdx.x; n < N_TOK; n += 256) {
        int e = g_expert_ids[n];
        int p = atomicAdd(&scur[e], 1);
        g_sorted[p] = n;
    }
}

// gather x rows into sorted order + bf16 hi/lo split
__global__ void k_gather(const float* __restrict__ x) {
    int p = blockIdx.x;
    int token = g_sorted[p];
    int c = threadIdx.x * 4;
    float4 v = *(const float4*)(x + (size_t)token * H + c);
    float vs[4] = {v.x, v.y, v.z, v.w};
    ushort hh[4], ll[4];
#pragma unroll
    for (int j = 0; j < 4; j++) {
        __nv_bfloat16 h = __float2bfloat16(vs[j]);
        __nv_bfloat16 l = __float2bfloat16(vs[j] - __bfloat162float(h));
        hh[j] = __bfloat16_as_ushort(h);
        ll[j] = __bfloat16_as_ushort(l);
    }
    size_t o = ((size_t)p * H + c) >> 2;
    ((uint2*)g_xs_hi)[o] = make_uint2((uint32_t)hh[0] | ((uint32_t)hh[1] << 16),
                                      (uint32_t)hh[2] | ((uint32_t)hh[3] << 16));
    ((uint2*)g_xs_lo)[o] = make_uint2((uint32_t)ll[0] | ((uint32_t)ll[1] << 16),
                                      (uint32_t)ll[2] | ((uint32_t)ll[3] << 16));
}

// elementwise fp32 -> bf16 hi/lo split
__global__ void k_split(const float* __restrict__ in,
                        __nv_bfloat16* __restrict__ oh,
                        __nv_bfloat16* __restrict__ ol, int n4) {
    int i = blockIdx.x * 256 + threadIdx.x;
    if (i >= n4) return;
    float4 v = ((const float4*)in)[i];
    float vs[4] = {v.x, v.y, v.z, v.w};
    ushort hh[4], ll[4];
#pragma unroll
    for (int j = 0; j < 4; j++) {
        __nv_bfloat16 h = __float2bfloat16(vs[j]);
        __nv_bfloat16 l = __float2bfloat16(vs[j] - __bfloat162float(h));
        hh[j] = __bfloat16_as_ushort(h);
        ll[j] = __bfloat16_as_ushort(l);
    }
    ((uint2*)oh)[i] = make_uint2((uint32_t)hh[0] | ((uint32_t)hh[1] << 16),
                                 (uint32_t)hh[2] | ((uint32_t)hh[3] << 16));
    ((uint2*)ol)[i] = make_uint2((uint32_t)ll[0] | ((uint32_t)ll[1] << 16),
                                 (uint32_t)ll[2] | ((uint32_t)ll[3] << 16));
}

// ---------------- GEMM1 stage load ----------------
__device__ __forceinline__ void g1_load(uint32_t s32, int s,
                                        const __nv_bfloat16* wh,
                                        const __nv_bfloat16* wl,
                                        int m0, int k0, int n0g, int tid) {
    uint32_t mbar = s32 + 512 + s * 8;
    uint32_t stg = s32 + STAGE_BASE + s * STG;
    if (tid == 0) mbar_expect(mbar, STAGE_BYTES);
    if (tid < 128) {
        int sr = m0 + tid;
        if (sr > N_TOK - 1) sr = N_TOK - 1;
        size_t off = (size_t)sr * H + k0;
        bulk_g2s(stg + OFF_AH + tid * A_ROWB, g_xs_hi + off, 128, mbar);
        bulk_g2s(stg + OFF_AL + tid * A_ROWB, g_xs_lo + off, 128, mbar);
    } else {
        int i = tid - 128;
        int kr = i & 63, prec = i >> 6;
        const __nv_bfloat16* w = prec ? wl : wh;
        uint32_t dst = stg + (prec ? OFF_BL : OFF_BH) + kr * B_ROWB;
        const __nv_bfloat16* src = w + (size_t)(k0 + kr) * F2 + n0g;
        bulk_g2s(dst, src, 128, mbar);         // gate cols
        bulk_g2s(dst + 128, src + IE, 128, mbar);  // up cols
    }
}

__global__ __launch_bounds__(256) void k_gemm1_mma() {
    int t = blockIdx.x;
    if (t >= g_num_tiles) return;
    int e = g_tile_expert[t];
    int m0 = g_offsets[e] + g_tile_mstart[t];
    int rows = g_offsets[e + 1] - m0;
    if (rows > 128) rows = 128;
    int n0g = blockIdx.y * 64;

    extern __shared__ char smraw[];
    uint32_t s32 = s2u(smraw);
    int tid = threadIdx.x;
    if (tid == 0) {
        mbar_init(s32 + 512, 1);
        mbar_init(s32 + 520, 1);
        mbar_init(s32 + 528, 1);
    }
    __syncthreads();
    fence_async();

    const __nv_bfloat16* wh = g_gup_hi + (size_t)e * H * F2;
    const __nv_bfloat16* wl = g_gup_lo + (size_t)e * H * F2;

    g1_load(s32, 0, wh, wl, m0, 0, n0g, tid);
    g1_load(s32, 1, wh, wl, m0, BK, n0g, tid);
    g1_load(s32, 2, wh, wl, m0, 2 * BK, n0g, tid);

    float acc[4][4][4];
#pragma unroll
    for (int i = 0; i < 4; i++)
#pragma unroll
        for (int j = 0; j < 4; j++)
#pragma unroll
            for (int r = 0; r < 4; r++) acc[i][j][r] = 0.f;

    int lane = tid & 31, w = tid >> 5;
    int warpM = w >> 2, warpN = w & 3;
    int p0 = warpN * 16, p1 = 64 + warpN * 16;

    const int NS = H / BK;  // 16
    for (int ki = 0; ki < NS; ki++) {
        int s = ki % 3;
        mbar_wait(s32 + 512 + s * 8, (ki / 3) & 1);
        uint32_t stg = s32 + STAGE_BASE + s * STG;
#pragma unroll
        for (int k16 = 0; k16 < 4; k16++)
            compute_k16(stg, lane, warpM, p0, p1, k16, acc);
        if (ki + 3 < NS) {
            __syncthreads();
            fence_async();
            g1_load(s32, s, wh, wl, m0, (ki + 3) * BK, n0g, tid);
        }
    }

    // epilogue: j=0,1 gate; j+2 up (same cols)
#pragma unroll
    for (int i = 0; i < 4; i++) {
        int r0 = warpM * 64 + i * 16 + (lane >> 2);
#pragma unroll
        for (int j = 0; j < 2; j++) {
            int col = n0g + warpN * 16 + j * 8 + (lane & 3) * 2;
#pragma unroll
            for (int hfa = 0; hfa < 2; hfa++) {
                int m = r0 + hfa * 8;
                if (m < rows) {
                    float g0 = acc[i][j][hfa * 2 + 0];
                    float g1 = acc[i][j][hfa * 2 + 1];
                    float u0 = acc[i][j + 2][hfa * 2 + 0];
                    float u1 = acc[i][j + 2][hfa * 2 + 1];
                    float v0 = g0 / (1.f + __expf(-g0)) * u0;
                    float v1 = g1 / (1.f + __expf(-g1)) * u1;
                    __nv_bfloat16 h0 = __float2bfloat16(v0);
                    __nv_bfloat16 h1 = __float2bfloat16(v1);
                    __nv_bfloat16 l0 = __float2bfloat16(v0 - __bfloat162float(h0));
                    __nv_bfloat16 l1 = __float2bfloat16(v1 - __bfloat162float(h1));
                    size_t o = ((size_t)(m0 + m) * IE + col) >> 1;
                    ((uint32_t*)g_inter_hi)[o] =
                        (uint32_t)__bfloat16_as_ushort(h0) |
                        ((uint32_t)__bfloat16_as_ushort(h1) << 16);
                    ((uint32_t*)g_inter_lo)[o] =
                        (uint32_t)__bfloat16_as_ushort(l0) |
                        ((uint32_t)__bfloat16_as_ushort(l1) << 16);
                }
            }
        }
    }
}

// ---------------- GEMM2 ----------------
__device__ __forceinline__ void g2_load(uint32_t s32, int s,
                                        const __nv_bfloat16* wh,
                                        const __nv_bfloat16* wl,
                                        int m0, int k0, int n0, int tid) {
    uint32_t mbar = s32 + 512 + s * 8;
    uint32_t stg = s32 + STAGE_BASE + s * STG;
    if (tid == 0) mbar_expect(mbar, STAGE_BYTES);
    if (tid < 128) {
        int sr = m0 + tid;
        if (sr > N_TOK - 1) sr = N_TOK - 1;
        size_t off = (size_t)sr * IE + k0;
        bulk_g2s(stg + OFF_AH + tid * A_ROWB, g_inter_hi + off, 128, mbar);
        bulk_g2s(stg + OFF_AL + tid * A_ROWB, g_inter_lo + off, 128, mbar);
    } else {
        int i = tid - 128;
        int kr = i & 63, prec = i >> 6;
        const __nv_bfloat16* w = prec ? wl : wh;
        uint32_t dst = stg + (prec ? OFF_BL : OFF_BH) + kr * B_ROWB;
        bulk_g2s(dst, w + (size_t)(k0 + kr) * H + n0, 256, mbar);
    }
}

__global__ __launch_bounds__(256) void k_gemm2_mma(float* __restrict__ out) {
    int t = blockIdx.x;
    if (t >= g_num_tiles) return;
    int e = g_tile_expert[t];
    int m0 = g_offsets[e] + g_tile_mstart[t];
    int rows = g_offsets[e + 1] - m0;
    if (rows > 128) rows = 128;
    int n0 = blockIdx.y * 128;

    extern __shared__ char smraw[];
    int* sRow = (int*)smraw;
    uint32_t s32 = s2u(smraw);
    int tid = threadIdx.x;
    if (tid < 128) sRow[tid] = (tid < rows) ? g_sorted[m0 + tid] : -1;
    if (tid == 0) {
        mbar_init(s32 + 512, 1);
        mbar_init(s32 + 520, 1);
        mbar_init(s32 + 528, 1);
    }
    __syncthreads();
    fence_async();

    const __nv_bfloat16* wh = g_dwn_hi + (size_t)e * IE * H;
    const __nv_bfloat16* wl = g_dwn_lo + (size_t)e * IE * H;

    g2_load(s32, 0, wh, wl, m0, 0, n0, tid);
    g2_load(s32, 1, wh, wl, m0, BK, n0, tid);
    g2_load(s32, 2, wh, wl, m0, 2 * BK, n0, tid);

    float acc[4][4][4];
#pragma unroll
    for (int i = 0; i < 4; i++)
#pragma unroll
        for (int j = 0; j < 4; j++)
#pragma unroll
            for (int r = 0; r < 4; r++) acc[i][j][r] = 0.f;

    int lane = tid & 31, w = tid >> 5;
    int warpM = w >> 2, warpN = w & 3;
    int p0 = warpN * 32, p1 = warpN * 32 + 16;

    const int NS = IE / BK;  // 8
    for (int ki = 0; ki < NS; ki++) {
        int s = ki % 3;
        mbar_wait(s32 + 512 + s * 8, (ki / 3) & 1);
        uint32_t stg = s32 + STAGE_BASE + s * STG;
#pragma unroll
        for (int k16 = 0; k16 < 4; k16++)
            compute_k16(stg, lane, warpM, p0, p1, k16, acc);
        if (ki + 3 < NS) {
            __syncthreads();
            fence_async();
            g2_load(s32, s, wh, wl, m0, (ki + 3) * BK, n0, tid);
        }
    }

#pragma unroll
    for (int i = 0; i < 4; i++) {
        int r0 = warpM * 64 + i * 16 + (lane >> 2);
#pragma unroll
        for (int hfa = 0; hfa < 2; hfa++) {
            int m = r0 + hfa * 8;
            if (m < rows) {
                int token = sRow[m];
                float* po = out + (size_t)token * H + n0;
#pragma unroll
                for (int j = 0; j < 4; j++) {
                    int col = warpN * 32 + j * 8 + (lane & 3) * 2;
                    *(float2*)(po + col) =
                        make_float2(acc[i][j][hfa * 2 + 0], acc[i][j][hfa * 2 + 1]);
                }
            }
        }
    }
}

// ---------------- launch ----------------
extern "C" void kernel_launch(void* const* d_in, const int* in_sizes, int n_in,
                              void* d_out, int out_size) {
    const float* hs  = (const float*)d_in[0];
    const int*   tok = (const int*)d_in[1];
    const float* mu  = (const float*)d_in[2];
    const float* gup = (const float*)d_in[3];
    const float* dwn = (const float*)d_in[4];
    const float* rw  = (const float*)d_in[5];
    float* out = (float*)d_out;
    (void)in_sizes; (void)n_in; (void)out_size;

    cudaFuncSetAttribute(k_gemm1_mma, cudaFuncAttributeMaxDynamicSharedMemorySize,
                         SMEM_TOT);
    cudaFuncSetAttribute(k_gemm2_mma, cudaFuncAttributeMaxDynamicSharedMemorySize,
                         SMEM_TOT);

    k_init<<<1, 32>>>();
    k_router<<<N_TOK / 8, 256>>>(mu, tok, rw);
    k_plan_scatter<<<1, 256>>>();
    k_gather<<<N_TOK, 256>>>(hs);
    {
        __nv_bfloat16 *gh, *gl, *dh, *dl;
        cudaGetSymbolAddress((void**)&gh, g_gup_hi);
        cudaGetSymbolAddress((void**)&gl, g_gup_lo);
        cudaGetSymbolAddress((void**)&dh, g_dwn_hi);
        cudaGetSymbolAddress((void**)&dl, g_dwn_lo);
        k_split<<<(E * H * F2 / 4 + 255) / 256, 256>>>(gup, gh, gl, E * H * F2 / 4);
        k_split<<<(E * IE * H / 4 + 255) / 256, 256>>>(dwn, dh, dl, E * IE * H / 4);
    }

    k_gemm1_mma<<<dim3(72, 8), 256, SMEM_TOT>>>();
    k_gemm2_mma<<<dim3(72, 8), 256, SMEM_TOT>>>(out);
}

// round 5
// speedup vs baseline: 1.2469x; 1.2469x over previous
#include <cuda_runtime.h>
#include <cuda_bf16.h>
#include <cstdint>

// ---------------- problem constants ----------------
#define N_TOK 8192
#define H     1024
#define E     8
#define IE    512
#define F2    1024
#define VOCAB 32000

// ---------------- scratch ----------------
__device__ int g_expert_ids[N_TOK];
__device__ int g_counts[E];
__device__ int g_offsets[E + 1];
__device__ int g_sorted[N_TOK];
__device__ int g_tile_expert[96];
__device__ int g_tile_mstart[96];
__device__ int g_num_tiles;

__device__ __nv_bfloat16 g_xs_hi[(size_t)N_TOK * H];   // sorted order
__device__ __nv_bfloat16 g_xs_lo[(size_t)N_TOK * H];
__device__ __nv_bfloat16 g_gup_hi[(size_t)E * H * F2];
__device__ __nv_bfloat16 g_gup_lo[(size_t)E * H * F2];
__device__ __nv_bfloat16 g_dwn_hi[(size_t)E * IE * H];
__device__ __nv_bfloat16 g_dwn_lo[(size_t)E * IE * H];
__device__ __nv_bfloat16 g_inter_hi[(size_t)N_TOK * IE];
__device__ __nv_bfloat16 g_inter_lo[(size_t)N_TOK * IE];

// ---------------- PTX helpers ----------------
__device__ __forceinline__ uint32_t s2u(const void* p) {
    uint32_t a;
    asm("{ .reg .u64 t; cvta.to.shared.u64 t, %1; cvt.u32.u64 %0, t; }"
        : "=r"(a) : "l"(p));
    return a;
}
__device__ __forceinline__ void cp16(uint32_t dst, const void* src) {
    asm volatile("cp.async.ca.shared.global [%0], [%1], 16;"
                 :: "r"(dst), "l"(src) : "memory");
}
__device__ __forceinline__ void cp_commit() {
    asm volatile("cp.async.commit_group;" ::: "memory");
}
__device__ __forceinline__ void cp_wait1() {
    asm volatile("cp.async.wait_group 1;" ::: "memory");
}
__device__ __forceinline__ void ldmx4(uint32_t* r, uint32_t a) {
    asm volatile("ldmatrix.sync.aligned.m8n8.x4.shared.b16 {%0,%1,%2,%3}, [%4];"
                 : "=r"(r[0]), "=r"(r[1]), "=r"(r[2]), "=r"(r[3]) : "r"(a));
}
__device__ __forceinline__ void ldmx4t(uint32_t* r, uint32_t a) {
    asm volatile("ldmatrix.sync.aligned.m8n8.x4.trans.shared.b16 {%0,%1,%2,%3}, [%4];"
                 : "=r"(r[0]), "=r"(r[1]), "=r"(r[2]), "=r"(r[3]) : "r"(a));
}
__device__ __forceinline__ void mma16816(float* d, const uint32_t* a,
                                         const uint32_t* b) {
    asm volatile(
        "mma.sync.aligned.m16n8k16.row.col.f32.bf16.bf16.f32 "
        "{%0,%1,%2,%3}, {%4,%5,%6,%7}, {%8,%9}, {%0,%1,%2,%3};"
        : "+f"(d[0]), "+f"(d[1]), "+f"(d[2]), "+f"(d[3])
        : "r"(a[0]), "r"(a[1]), "r"(a[2]), "r"(a[3]), "r"(b[0]), "r"(b[1]));
}

// ---------------- smem layout (BK = 32) ----------------
#define BK     32
#define A_ROWB 80    // 32 bf16 (64B) + 16B pad
#define B_ROWB 272   // 128 bf16 (256B) + 16B pad
#define OFF_AH 0
#define OFF_AL 10240
#define OFF_BH 20480
#define OFF_BL 29184
#define STG    37888
#define STAGE_BASE 512
#define SMEM_TOT (STAGE_BASE + 3 * STG)   // 114176

__device__ __forceinline__ uint32_t a_addr(uint32_t base, int lane, int mbase,
                                           int k16) {
    int row = mbase + (lane & 15);
    return base + row * A_ROWB + k16 * 32 + ((lane >> 4) << 4);
}
__device__ __forceinline__ uint32_t b_addr(uint32_t base, int lane, int nbase,
                                           int k16) {
    int krow = k16 * 16 + (lane & 15);
    return base + krow * B_ROWB + nbase * 2 + ((lane >> 4) << 4);
}

// warp tile 32x32: one k16 step = 8 ldmatrix.x4 + 24 HMMA
__device__ __forceinline__ void compute_k16(uint32_t stg, int lane, int warpM,
                                            int p0, int p1, int k16,
                                            float acc[2][4][4]) {
    uint32_t ah[2][4], al[2][4], bh[2][4], bl[2][4];
#pragma unroll
    for (int i = 0; i < 2; i++) {
        ldmx4(ah[i], a_addr(stg + OFF_AH, lane, warpM * 32 + i * 16, k16));
        ldmx4(al[i], a_addr(stg + OFF_AL, lane, warpM * 32 + i * 16, k16));
    }
    ldmx4t(bh[0], b_addr(stg + OFF_BH, lane, p0, k16));
    ldmx4t(bh[1], b_addr(stg + OFF_BH, lane, p1, k16));
    ldmx4t(bl[0], b_addr(stg + OFF_BL, lane, p0, k16));
    ldmx4t(bl[1], b_addr(stg + OFF_BL, lane, p1, k16));
#pragma unroll
    for (int i = 0; i < 2; i++) {
#pragma unroll
        for (int j = 0; j < 4; j++) {
            const uint32_t* bhp = &bh[j >> 1][(j & 1) * 2];
            const uint32_t* blp = &bl[j >> 1][(j & 1) * 2];
            mma16816(acc[i][j], ah[i], bhp);
            mma16816(acc[i][j], ah[i], blp);
            mma16816(acc[i][j], al[i], bhp);
        }
    }
}

// ---------------- small kernels ----------------
__global__ void k_init() {
    if (threadIdx.x < E) g_counts[threadIdx.x] = 0;
}

__global__ void k_router(const float* __restrict__ mu, const int* __restrict__ tok,
                         const float* __restrict__ w) {
    __shared__ float ws[E * H];
    int tid = threadIdx.x;
    for (int i = tid; i < E * H; i += 256) ws[i] = w[i];
    __syncthreads();
    int warp = tid >> 5, lane = tid & 31;
    int n = blockIdx.x * 8 + warp;
    const float* mrow = mu + (size_t)n * H;
    float acc[E];
#pragma unroll
    for (int e = 0; e < E; e++) acc[e] = 0.f;
    for (int h = lane; h < H; h += 32) {
        float m = mrow[h];
#pragma unroll
        for (int e = 0; e < E; e++) acc[e] += m * ws[e * H + h];
    }
#pragma unroll
    for (int off = 16; off > 0; off >>= 1)
#pragma unroll
        for (int e = 0; e < E; e++)
            acc[e] += __shfl_down_sync(0xffffffffu, acc[e], off);
    if (lane == 0) {
        int id = tok[n];
        if (id < 0) id = 0;
        if (id >= VOCAB) id = VOCAB - 1;
        int base = id & (E - 1);
        float best = -1e30f;
        int be = 0;
#pragma unroll
        for (int e = 0; e < E; e++) {
            float v = acc[e] + (e == base ? 10.0f : 0.0f);
            if (v > best) { best = v; be = e; }
        }
        g_expert_ids[n] = be;
        atomicAdd(&g_counts[be], 1);
    }
}

__global__ void k_plan_scatter() {
    __shared__ int scur[E];
    if (threadIdx.x == 0) {
        int off = 0;
        for (int e = 0; e < E; e++) {
            g_offsets[e] = off;
            scur[e] = off;
            off += g_counts[e];
        }
        g_offsets[E] = off;
        int tt = 0;
        for (int e = 0; e < E; e++) {
            int cnt = g_counts[e];
            for (int ms = 0; ms < cnt; ms += 128) {
                g_tile_expert[tt] = e;
                g_tile_mstart[tt] = ms;
                tt++;
            }
        }
        g_num_tiles = tt;
    }
    __syncthreads();
    for (int n = threadIdx.x; n < N_TOK; n += 256) {
        int e = g_expert_ids[n];
        int p = atomicAdd(&scur[e], 1);
        g_sorted[p] = n;
    }
}

// gather x rows into sorted order + bf16 hi/lo split
__global__ void k_gather(const float* __restrict__ x) {
    int p = blockIdx.x;
    int token = g_sorted[p];
    int c = threadIdx.x * 4;
    float4 v = *(const float4*)(x + (size_t)token * H + c);
    float vs[4] = {v.x, v.y, v.z, v.w};
    ushort hh[4], ll[4];
#pragma unroll
    for (int j = 0; j < 4; j++) {
        __nv_bfloat16 h = __float2bfloat16(vs[j]);
        __nv_bfloat16 l = __float2bfloat16(vs[j] - __bfloat162float(h));
        hh[j] = __bfloat16_as_ushort(h);
        ll[j] = __bfloat16_as_ushort(l);
    }
    size_t o = ((size_t)p * H + c) >> 2;
    ((uint2*)g_xs_hi)[o] = make_uint2((uint32_t)hh[0] | ((uint32_t)hh[1] << 16),
                                      (uint32_t)hh[2] | ((uint32_t)hh[3] << 16));
    ((uint2*)g_xs_lo)[o] = make_uint2((uint32_t)ll[0] | ((uint32_t)ll[1] << 16),
                                      (uint32_t)ll[2] | ((uint32_t)ll[3] << 16));
}

// elementwise fp32 -> bf16 hi/lo split
__global__ void k_split(const float* __restrict__ in,
                        __nv_bfloat16* __restrict__ oh,
                        __nv_bfloat16* __restrict__ ol, int n4) {
    int i = blockIdx.x * 256 + threadIdx.x;
    if (i >= n4) return;
    float4 v = ((const float4*)in)[i];
    float vs[4] = {v.x, v.y, v.z, v.w};
    ushort hh[4], ll[4];
#pragma unroll
    for (int j = 0; j < 4; j++) {
        __nv_bfloat16 h = __float2bfloat16(vs[j]);
        __nv_bfloat16 l = __float2bfloat16(vs[j] - __bfloat162float(h));
        hh[j] = __bfloat16_as_ushort(h);
        ll[j] = __bfloat16_as_ushort(l);
    }
    ((uint2*)oh)[i] = make_uint2((uint32_t)hh[0] | ((uint32_t)hh[1] << 16),
                                 (uint32_t)hh[2] | ((uint32_t)hh[3] << 16));
    ((uint2*)ol)[i] = make_uint2((uint32_t)ll[0] | ((uint32_t)ll[1] << 16),
                                 (uint32_t)ll[2] | ((uint32_t)ll[3] << 16));
}

// ---------------- GEMM1 stage load (512 threads, 4 cp16 each) --------------
__device__ __forceinline__ void g1_load(uint32_t sb, int s,
                                        const __nv_bfloat16* wh,
                                        const __nv_bfloat16* wl,
                                        int m0, int k0, int n0g, int tid) {
    uint32_t stg = sb + s * STG;
    // A: row = tid>>2 (0..127), chunk c = tid&3 (16B of 64B row)
    int row = tid >> 2, c = tid & 3;
    int sr = m0 + row;
    if (sr > N_TOK - 1) sr = N_TOK - 1;
    size_t so = (size_t)sr * H + k0 + c * 8;
    cp16(stg + OFF_AH + row * A_ROWB + c * 16, g_xs_hi + so);
    cp16(stg + OFF_AL + row * A_ROWB + c * 16, g_xs_lo + so);
    // B: krow = tid>>4 (0..31), chunk c2 = tid&15 (16B of 256B row)
    int kr = tid >> 4, c2 = tid & 15;
    int col = (c2 < 8) ? (n0g + c2 * 8) : (IE + n0g + (c2 - 8) * 8);
    size_t wo = (size_t)(k0 + kr) * F2 + col;
    cp16(stg + OFF_BH + kr * B_ROWB + c2 * 16, wh + wo);
    cp16(stg + OFF_BL + kr * B_ROWB + c2 * 16, wl + wo);
}

__global__ __launch_bounds__(512) void k_gemm1_mma() {
    int t = blockIdx.x;
    if (t >= g_num_tiles) return;
    int e = g_tile_expert[t];
    int m0 = g_offsets[e] + g_tile_mstart[t];
    int rows = g_offsets[e + 1] - m0;
    if (rows > 128) rows = 128;
    int n0g = blockIdx.y * 64;

    extern __shared__ char smraw[];
    uint32_t sb = s2u(smraw) + STAGE_BASE;
    int tid = threadIdx.x;

    const __nv_bfloat16* wh = g_gup_hi + (size_t)e * H * F2;
    const __nv_bfloat16* wl = g_gup_lo + (size_t)e * H * F2;

    g1_load(sb, 0, wh, wl, m0, 0, n0g, tid);
    cp_commit();
    g1_load(sb, 1, wh, wl, m0, BK, n0g, tid);
    cp_commit();

    float acc[2][4][4];
#pragma unroll
    for (int i = 0; i < 2; i++)
#pragma unroll
        for (int j = 0; j < 4; j++)
#pragma unroll
            for (int r = 0; r < 4; r++) acc[i][j][r] = 0.f;

    int lane = tid & 31, w = tid >> 5;
    int warpM = w >> 2, warpN = w & 3;          // 4 x 4 warps
    int p0 = warpN * 16, p1 = 64 + warpN * 16;  // gate / up halves

    const int NS = H / BK;  // 32
    for (int ki = 0; ki < NS; ki++) {
        cp_wait1();
        __syncthreads();
        if (ki + 2 < NS) g1_load(sb, (ki + 2) % 3, wh, wl, m0, (ki + 2) * BK, n0g, tid);
        cp_commit();
        uint32_t stg = sb + (ki % 3) * STG;
        compute_k16(stg, lane, warpM, p0, p1, 0, acc);
        compute_k16(stg, lane, warpM, p0, p1, 1, acc);
    }

    // epilogue: j=0,1 gate; j+2 up (same inter cols)
#pragma unroll
    for (int i = 0; i < 2; i++) {
        int r0 = warpM * 32 + i * 16 + (lane >> 2);
#pragma unroll
        for (int j = 0; j < 2; j++) {
            int col = n0g + warpN * 16 + j * 8 + (lane & 3) * 2;
#pragma unroll
            for (int hfa = 0; hfa < 2; hfa++) {
                int m = r0 + hfa * 8;
                if (m < rows) {
                    float g0 = acc[i][j][hfa * 2 + 0];
                    float g1 = acc[i][j][hfa * 2 + 1];
                    float u0 = acc[i][j + 2][hfa * 2 + 0];
                    float u1 = acc[i][j + 2][hfa * 2 + 1];
                    float v0 = g0 / (1.f + __expf(-g0)) * u0;
                    float v1 = g1 / (1.f + __expf(-g1)) * u1;
                    __nv_bfloat16 h0 = __float2bfloat16(v0);
                    __nv_bfloat16 h1 = __float2bfloat16(v1);
                    __nv_bfloat16 l0 = __float2bfloat16(v0 - __bfloat162float(h0));
                    __nv_bfloat16 l1 = __float2bfloat16(v1 - __bfloat162float(h1));
                    size_t o = ((size_t)(m0 + m) * IE + col) >> 1;
                    ((uint32_t*)g_inter_hi)[o] =
                        (uint32_t)__bfloat16_as_ushort(h0) |
                        ((uint32_t)__bfloat16_as_ushort(h1) << 16);
                    ((uint32_t*)g_inter_lo)[o] =
                        (uint32_t)__bfloat16_as_ushort(l0) |
                        ((uint32_t)__bfloat16_as_ushort(l1) << 16);
                }
            }
        }
    }
}

// ---------------- GEMM2 ----------------
__device__ __forceinline__ void g2_load(uint32_t sb, int s,
                                        const __nv_bfloat16* wh,
                                        const __nv_bfloat16* wl,
                                        int m0, int k0, int n0, int tid) {
    uint32_t stg = sb + s * STG;
    int row = tid >> 2, c = tid & 3;
    int sr = m0 + row;
    if (sr > N_TOK - 1) sr = N_TOK - 1;
    size_t so = (size_t)sr * IE + k0 + c * 8;
    cp16(stg + OFF_AH + row * A_ROWB + c * 16, g_inter_hi + so);
    cp16(stg + OFF_AL + row * A_ROWB + c * 16, g_inter_lo + so);
    int kr = tid >> 4, c2 = tid & 15;
    size_t wo = (size_t)(k0 + kr) * H + n0 + c2 * 8;
    cp16(stg + OFF_BH + kr * B_ROWB + c2 * 16, wh + wo);
    cp16(stg + OFF_BL + kr * B_ROWB + c2 * 16, wl + wo);
}

__global__ __launch_bounds__(512) void k_gemm2_mma(float* __restrict__ out) {
    int t = blockIdx.x;
    if (t >= g_num_tiles) return;
    int e = g_tile_expert[t];
    int m0 = g_offsets[e] + g_tile_mstart[t];
    int rows = g_offsets[e + 1] - m0;
    if (rows > 128) rows = 128;
    int n0 = blockIdx.y * 128;

    extern __shared__ char smraw[];
    int* sRow = (int*)smraw;
    uint32_t sb = s2u(smraw) + STAGE_BASE;
    int tid = threadIdx.x;
    if (tid < 128) sRow[tid] = (tid < rows) ? g_sorted[m0 + tid] : -1;
    __syncthreads();

    const __nv_bfloat16* wh = g_dwn_hi + (size_t)e * IE * H;
    const __nv_bfloat16* wl = g_dwn_lo + (size_t)e * IE * H;

    g2_load(sb, 0, wh, wl, m0, 0, n0, tid);
    cp_commit();
    g2_load(sb, 1, wh, wl, m0, BK, n0, tid);
    cp_commit();

    float acc[2][4][4];
#pragma unroll
    for (int i = 0; i < 2; i++)
#pragma unroll
        for (int j = 0; j < 4; j++)
#pragma unroll
            for (int r = 0; r < 4; r++) acc[i][j][r] = 0.f;

    int lane = tid & 31, w = tid >> 5;
    int warpM = w >> 2, warpN = w & 3;
    int p0 = warpN * 32, p1 = warpN * 32 + 16;

    const int NS = IE / BK;  // 16
    for (int ki = 0; ki < NS; ki++) {
        cp_wait1();
        __syncthreads();
        if (ki + 2 < NS) g2_load(sb, (ki + 2) % 3, wh, wl, m0, (ki + 2) * BK, n0, tid);
        cp_commit();
        uint32_t stg = sb + (ki % 3) * STG;
        compute_k16(stg, lane, warpM, p0, p1, 0, acc);
        compute_k16(stg, lane, warpM, p0, p1, 1, acc);
    }

#pragma unroll
    for (int i = 0; i < 2; i++) {
        int r0 = warpM * 32 + i * 16 + (lane >> 2);
#pragma unroll
        for (int hfa = 0; hfa < 2; hfa++) {
            int m = r0 + hfa * 8;
            if (m < rows) {
                int token = sRow[m];
                float* po = out + (size_t)token * H + n0;
#pragma unroll
                for (int j = 0; j < 4; j++) {
                    int col = warpN * 32 + j * 8 + (lane & 3) * 2;
                    *(float2*)(po + col) =
                        make_float2(acc[i][j][hfa * 2 + 0], acc[i][j][hfa * 2 + 1]);
                }
            }
        }
    }
}

// ---------------- launch ----------------
extern "C" void kernel_launch(void* const* d_in, const int* in_sizes, int n_in,
                              void* d_out, int out_size) {
    const float* hs  = (const float*)d_in[0];
    const int*   tok = (const int*)d_in[1];
    const float* mu  = (const float*)d_in[2];
    const float* gup = (const float*)d_in[3];
    const float* dwn = (const float*)d_in[4];
    const float* rw  = (const float*)d_in[5];
    float* out = (float*)d_out;
    (void)in_sizes; (void)n_in; (void)out_size;

    cudaFuncSetAttribute(k_gemm1_mma, cudaFuncAttributeMaxDynamicSharedMemorySize,
                         SMEM_TOT);
    cudaFuncSetAttribute(k_gemm2_mma, cudaFuncAttributeMaxDynamicSharedMemorySize,
                         SMEM_TOT);

    k_init<<<1, 32>>>();
    k_router<<<N_TOK / 8, 256>>>(mu, tok, rw);
    k_plan_scatter<<<1, 256>>>();
    k_gather<<<N_TOK, 256>>>(hs);
    {
        __nv_bfloat16 *gh, *gl, *dh, *dl;
        cudaGetSymbolAddress((void**)&gh, g_gup_hi);
        cudaGetSymbolAddress((void**)&gl, g_gup_lo);
        cudaGetSymbolAddress((void**)&dh, g_dwn_hi);
        cudaGetSymbolAddress((void**)&dl, g_dwn_lo);
        k_split<<<(E * H * F2 / 4 + 255) / 256, 256>>>(gup, gh, gl, E * H * F2 / 4);
        k_split<<<(E * IE * H / 4 + 255) / 256, 256>>>(dwn, dh, dl, E * IE * H / 4);
    }

    k_gemm1_mma<<<dim3(72, 8), 512, SMEM_TOT>>>();
    k_gemm2_mma<<<dim3(72, 8), 512, SMEM_TOT>>>(out);
}

// round 6
// speedup vs baseline: 1.5500x; 1.2431x over previous
#include <cuda_runtime.h>
#include <cuda_fp16.h>
#include <cstdint>

// ---------------- problem constants ----------------
#define N_TOK 8192
#define H     1024
#define E     8
#define IE    512
#define F2    1024
#define VOCAB 32000

// ---------------- scratch ----------------
__device__ int g_expert_ids[N_TOK];
__device__ int g_counts[E];
__device__ int g_offsets[E + 1];
__device__ int g_sorted[N_TOK];
__device__ int g_tile_expert[96];
__device__ int g_tile_mstart[96];
__device__ int g_num_tiles;

__device__ __half g_xs_hi[(size_t)N_TOK * H];   // sorted order
__device__ __half g_xs_lo[(size_t)N_TOK * H];
__device__ __half g_gup_h[(size_t)E * H * F2];  // single fp16 weights
__device__ __half g_dwn_h[(size_t)E * IE * H];
__device__ __half g_inter_hi[(size_t)N_TOK * IE];
__device__ __half g_inter_lo[(size_t)N_TOK * IE];

// ---------------- PTX helpers ----------------
__device__ __forceinline__ uint32_t s2u(const void* p) {
    uint32_t a;
    asm("{ .reg .u64 t; cvta.to.shared.u64 t, %1; cvt.u32.u64 %0, t; }"
        : "=r"(a) : "l"(p));
    return a;
}
__device__ __forceinline__ void cp16(uint32_t dst, const void* src) {
    asm volatile("cp.async.ca.shared.global [%0], [%1], 16;"
                 :: "r"(dst), "l"(src) : "memory");
}
__device__ __forceinline__ void cp_commit() {
    asm volatile("cp.async.commit_group;" ::: "memory");
}
__device__ __forceinline__ void cp_wait1() {
    asm volatile("cp.async.wait_group 1;" ::: "memory");
}
__device__ __forceinline__ void ldmx4(uint32_t* r, uint32_t a) {
    asm volatile("ldmatrix.sync.aligned.m8n8.x4.shared.b16 {%0,%1,%2,%3}, [%4];"
                 : "=r"(r[0]), "=r"(r[1]), "=r"(r[2]), "=r"(r[3]) : "r"(a));
}
__device__ __forceinline__ void ldmx4t(uint32_t* r, uint32_t a) {
    asm volatile("ldmatrix.sync.aligned.m8n8.x4.trans.shared.b16 {%0,%1,%2,%3}, [%4];"
                 : "=r"(r[0]), "=r"(r[1]), "=r"(r[2]), "=r"(r[3]) : "r"(a));
}
__device__ __forceinline__ void mma16816(float* d, const uint32_t* a,
                                         const uint32_t* b) {
    asm volatile(
        "mma.sync.aligned.m16n8k16.row.col.f32.f16.f16.f32 "
        "{%0,%1,%2,%3}, {%4,%5,%6,%7}, {%8,%9}, {%0,%1,%2,%3};"
        : "+f"(d[0]), "+f"(d[1]), "+f"(d[2]), "+f"(d[3])
        : "r"(a[0]), "r"(a[1]), "r"(a[2]), "r"(a[3]), "r"(b[0]), "r"(b[1]));
}

// ---------------- smem layout (BK = 32) ----------------
#define BK     32
#define A_ROWB 80    // 32 fp16 (64B) + 16B pad
#define B_ROWB 272   // 128 fp16 (256B) + 16B pad
#define OFF_AH 0
#define OFF_AL 10240
#define OFF_BH 20480
#define STG    29184
#define STAGE_BASE 512
#define SMEM_TOT (STAGE_BASE + 3 * STG)   // 88064

__device__ __forceinline__ uint32_t a_addr(uint32_t base, int lane, int mbase,
                                           int k16) {
    int row = mbase + (lane & 15);
    return base + row * A_ROWB + k16 * 32 + ((lane >> 4) << 4);
}
__device__ __forceinline__ uint32_t b_addr(uint32_t base, int lane, int nbase,
                                           int k16) {
    int krow = k16 * 16 + (lane & 15);
    return base + krow * B_ROWB + nbase * 2 + ((lane >> 4) << 4);
}

// warp tile 32x32: one k16 step = 6 ldmatrix.x4 + 16 HMMA
__device__ __forceinline__ void compute_k16(uint32_t stg, int lane, int warpM,
                                            int p0, int p1, int k16,
                                            float acc[2][4][4]) {
    uint32_t ah[2][4], al[2][4], bh[2][4];
#pragma unroll
    for (int i = 0; i < 2; i++) {
        ldmx4(ah[i], a_addr(stg + OFF_AH, lane, warpM * 32 + i * 16, k16));
        ldmx4(al[i], a_addr(stg + OFF_AL, lane, warpM * 32 + i * 16, k16));
    }
    ldmx4t(bh[0], b_addr(stg + OFF_BH, lane, p0, k16));
    ldmx4t(bh[1], b_addr(stg + OFF_BH, lane, p1, k16));
#pragma unroll
    for (int i = 0; i < 2; i++) {
#pragma unroll
        for (int j = 0; j < 4; j++) {
            const uint32_t* bhp = &bh[j >> 1][(j & 1) * 2];
            mma16816(acc[i][j], ah[i], bhp);
            mma16816(acc[i][j], al[i], bhp);
        }
    }
}

// ---------------- small kernels ----------------
__global__ void k_init() {
    if (threadIdx.x < E) g_counts[threadIdx.x] = 0;
}

__global__ void k_router(const float* __restrict__ mu, const int* __restrict__ tok,
                         const float* __restrict__ w) {
    __shared__ float ws[E * H];
    int tid = threadIdx.x;
    for (int i = tid; i < E * H; i += 256) ws[i] = w[i];
    __syncthreads();
    int warp = tid >> 5, lane = tid & 31;
    int n = blockIdx.x * 8 + warp;
    const float* mrow = mu + (size_t)n * H;
    float acc[E];
#pragma unroll
    for (int e = 0; e < E; e++) acc[e] = 0.f;
    for (int h = lane; h < H; h += 32) {
        float m = mrow[h];
#pragma unroll
        for (int e = 0; e < E; e++) acc[e] += m * ws[e * H + h];
    }
#pragma unroll
    for (int off = 16; off > 0; off >>= 1)
#pragma unroll
        for (int e = 0; e < E; e++)
            acc[e] += __shfl_down_sync(0xffffffffu, acc[e], off);
    if (lane == 0) {
        int id = tok[n];
        if (id < 0) id = 0;
        if (id >= VOCAB) id = VOCAB - 1;
        int base = id & (E - 1);
        float best = -1e30f;
        int be = 0;
#pragma unroll
        for (int e = 0; e < E; e++) {
            float v = acc[e] + (e == base ? 10.0f : 0.0f);
            if (v > best) { best = v; be = e; }
        }
        g_expert_ids[n] = be;
        atomicAdd(&g_counts[be], 1);
    }
}

__global__ void k_plan_scatter() {
    __shared__ int scur[E];
    if (threadIdx.x == 0) {
        int off = 0;
        for (int e = 0; e < E; e++) {
            g_offsets[e] = off;
            scur[e] = off;
            off += g_counts[e];
        }
        g_offsets[E] = off;
        int tt = 0;
        for (int e = 0; e < E; e++) {
            int cnt = g_counts[e];
            for (int ms = 0; ms < cnt; ms += 128) {
                g_tile_expert[tt] = e;
                g_tile_mstart[tt] = ms;
                tt++;
            }
        }
        g_num_tiles = tt;
    }
    __syncthreads();
    for (int n = threadIdx.x; n < N_TOK; n += 256) {
        int e = g_expert_ids[n];
        int p = atomicAdd(&scur[e], 1);
        g_sorted[p] = n;
    }
}

// gather x rows into sorted order + fp16 hi/lo split
__global__ void k_gather(const float* __restrict__ x) {
    int p = blockIdx.x;
    int token = g_sorted[p];
    int c = threadIdx.x * 4;
    float4 v = *(const float4*)(x + (size_t)token * H + c);
    float vs[4] = {v.x, v.y, v.z, v.w};
    ushort hh[4], ll[4];
#pragma unroll
    for (int j = 0; j < 4; j++) {
        __half h = __float2half_rn(vs[j]);
        __half l = __float2half_rn(vs[j] - __half2float(h));
        hh[j] = __half_as_ushort(h);
        ll[j] = __half_as_ushort(l);
    }
    size_t o = ((size_t)p * H + c) >> 2;
    ((uint2*)g_xs_hi)[o] = make_uint2((uint32_t)hh[0] | ((uint32_t)hh[1] << 16),
                                      (uint32_t)hh[2] | ((uint32_t)hh[3] << 16));
    ((uint2*)g_xs_lo)[o] = make_uint2((uint32_t)ll[0] | ((uint32_t)ll[1] << 16),
                                      (uint32_t)ll[2] | ((uint32_t)ll[3] << 16));
}

// fp32 -> fp16 convert (weights)
__global__ void k_cvt(const float* __restrict__ in, __half* __restrict__ out,
                      int n4) {
    int i = blockIdx.x * 256 + threadIdx.x;
    if (i >= n4) return;
    float4 v = ((const float4*)in)[i];
    __half2 a = __floats2half2_rn(v.x, v.y);
    __half2 b = __floats2half2_rn(v.z, v.w);
    ((uint2*)out)[i] = make_uint2(*(uint32_t*)&a, *(uint32_t*)&b);
}

// ---------------- GEMM1 stage load (512 threads, 3 cp16 each) --------------
__device__ __forceinline__ void g1_load(uint32_t sb, int s,
                                        const __half* wh,
                                        int m0, int k0, int n0g, int tid) {
    uint32_t stg = sb + s * STG;
    // A: row = tid>>2 (0..127), chunk c = tid&3 (16B of 64B row)
    int row = tid >> 2, c = tid & 3;
    int sr = m0 + row;
    if (sr > N_TOK - 1) sr = N_TOK - 1;
    size_t so = (size_t)sr * H + k0 + c * 8;
    cp16(stg + OFF_AH + row * A_ROWB + c * 16, g_xs_hi + so);
    cp16(stg + OFF_AL + row * A_ROWB + c * 16, g_xs_lo + so);
    // B: krow = tid>>4 (0..31), chunk c2 = tid&15 (16B of 256B row)
    int kr = tid >> 4, c2 = tid & 15;
    int col = (c2 < 8) ? (n0g + c2 * 8) : (IE + n0g + (c2 - 8) * 8);
    cp16(stg + OFF_BH + kr * B_ROWB + c2 * 16, wh + (size_t)(k0 + kr) * F2 + col);
}

__global__ __launch_bounds__(512) void k_gemm1_mma() {
    int t = blockIdx.x;
    if (t >= g_num_tiles) return;
    int e = g_tile_expert[t];
    int m0 = g_offsets[e] + g_tile_mstart[t];
    int rows = g_offsets[e + 1] - m0;
    if (rows > 128) rows = 128;
    int n0g = blockIdx.y * 64;

    extern __shared__ char smraw[];
    uint32_t sb = s2u(smraw) + STAGE_BASE;
    int tid = threadIdx.x;

    const __half* wh = g_gup_h + (size_t)e * H * F2;

    g1_load(sb, 0, wh, m0, 0, n0g, tid);
    cp_commit();
    g1_load(sb, 1, wh, m0, BK, n0g, tid);
    cp_commit();

    float acc[2][4][4];
#pragma unroll
    for (int i = 0; i < 2; i++)
#pragma unroll
        for (int j = 0; j < 4; j++)
#pragma unroll
            for (int r = 0; r < 4; r++) acc[i][j][r] = 0.f;

    int lane = tid & 31, w = tid >> 5;
    int warpM = w >> 2, warpN = w & 3;          // 4 x 4 warps
    int p0 = warpN * 16, p1 = 64 + warpN * 16;  // gate / up halves

    const int NS = H / BK;  // 32
    for (int ki = 0; ki < NS; ki++) {
        cp_wait1();
        __syncthreads();
        if (ki + 2 < NS) g1_load(sb, (ki + 2) % 3, wh, m0, (ki + 2) * BK, n0g, tid);
        cp_commit();
        uint32_t stg = sb + (ki % 3) * STG;
        compute_k16(stg, lane, warpM, p0, p1, 0, acc);
        compute_k16(stg, lane, warpM, p0, p1, 1, acc);
    }

    // epilogue: j=0,1 gate; j+2 up (same inter cols)
#pragma unroll
    for (int i = 0; i < 2; i++) {
        int r0 = warpM * 32 + i * 16 + (lane >> 2);
#pragma unroll
        for (int j = 0; j < 2; j++) {
            int col = n0g + warpN * 16 + j * 8 + (lane & 3) * 2;
#pragma unroll
            for (int hfa = 0; hfa < 2; hfa++) {
                int m = r0 + hfa * 8;
                if (m < rows) {
                    float g0 = acc[i][j][hfa * 2 + 0];
                    float g1 = acc[i][j][hfa * 2 + 1];
                    float u0 = acc[i][j + 2][hfa * 2 + 0];
                    float u1 = acc[i][j + 2][hfa * 2 + 1];
                    float v0 = g0 / (1.f + __expf(-g0)) * u0;
                    float v1 = g1 / (1.f + __expf(-g1)) * u1;
                    __half h0 = __float2half_rn(v0);
                    __half h1 = __float2half_rn(v1);
                    __half l0 = __float2half_rn(v0 - __half2float(h0));
                    __half l1 = __float2half_rn(v1 - __half2float(h1));
                    size_t o = ((size_t)(m0 + m) * IE + col) >> 1;
                    ((uint32_t*)g_inter_hi)[o] =
                        (uint32_t)__half_as_ushort(h0) |
                        ((uint32_t)__half_as_ushort(h1) << 16);
                    ((uint32_t*)g_inter_lo)[o] =
                        (uint32_t)__half_as_ushort(l0) |
                        ((uint32_t)__half_as_ushort(l1) << 16);
                }
            }
        }
    }
}

// ---------------- GEMM2 ----------------
__device__ __forceinline__ void g2_load(uint32_t sb, int s,
                                        const __half* wh,
                                        int m0, int k0, int n0, int tid) {
    uint32_t stg = sb + s * STG;
    int row = tid >> 2, c = tid & 3;
    int sr = m0 + row;
    if (sr > N_TOK - 1) sr = N_TOK - 1;
    size_t so = (size_t)sr * IE + k0 + c * 8;
    cp16(stg + OFF_AH + row * A_ROWB + c * 16, g_inter_hi + so);
    cp16(stg + OFF_AL + row * A_ROWB + c * 16, g_inter_lo + so);
    int kr = tid >> 4, c2 = tid & 15;
    cp16(stg + OFF_BH + kr * B_ROWB + c2 * 16,
         wh + (size_t)(k0 + kr) * H + n0 + c2 * 8);
}

__global__ __launch_bounds__(512) void k_gemm2_mma(float* __restrict__ out) {
    int t = blockIdx.x;
    if (t >= g_num_tiles) return;
    int e = g_tile_expert[t];
    int m0 = g_offsets[e] + g_tile_mstart[t];
    int rows = g_offsets[e + 1] - m0;
    if (rows > 128) rows = 128;
    int n0 = blockIdx.y * 128;

    extern __shared__ char smraw[];
    int* sRow = (int*)smraw;
    uint32_t sb = s2u(smraw) + STAGE_BASE;
    int tid = threadIdx.x;
    if (tid < 128) sRow[tid] = (tid < rows) ? g_sorted[m0 + tid] : -1;
    __syncthreads();

    const __half* wh = g_dwn_h + (size_t)e * IE * H;

    g2_load(sb, 0, wh, m0, 0, n0, tid);
    cp_commit();
    g2_load(sb, 1, wh, m0, BK, n0, tid);
    cp_commit();

    float acc[2][4][4];
#pragma unroll
    for (int i = 0; i < 2; i++)
#pragma unroll
        for (int j = 0; j < 4; j++)
#pragma unroll
            for (int r = 0; r < 4; r++) acc[i][j][r] = 0.f;

    int lane = tid & 31, w = tid >> 5;
    int warpM = w >> 2, warpN = w & 3;
    int p0 = warpN * 32, p1 = warpN * 32 + 16;

    const int NS = IE / BK;  // 16
    for (int ki = 0; ki < NS; ki++) {
        cp_wait1();
        __syncthreads();
        if (ki + 2 < NS) g2_load(sb, (ki + 2) % 3, wh, m0, (ki + 2) * BK, n0, tid);
        cp_commit();
        uint32_t stg = sb + (ki % 3) * STG;
        compute_k16(stg, lane, warpM, p0, p1, 0, acc);
        compute_k16(stg, lane, warpM, p0, p1, 1, acc);
    }

#pragma unroll
    for (int i = 0; i < 2; i++) {
        int r0 = warpM * 32 + i * 16 + (lane >> 2);
#pragma unroll
        for (int hfa = 0; hfa < 2; hfa++) {
            int m = r0 + hfa * 8;
            if (m < rows) {
                int token = sRow[m];
                float* po = out + (size_t)token * H + n0;
#pragma unroll
                for (int j = 0; j < 4; j++) {
                    int col = warpN * 32 + j * 8 + (lane & 3) * 2;
                    *(float2*)(po + col) =
                        make_float2(acc[i][j][hfa * 2 + 0], acc[i][j][hfa * 2 + 1]);
                }
            }
        }
    }
}

// ---------------- launch ----------------
extern "C" void kernel_launch(void* const* d_in, const int* in_sizes, int n_in,
                              void* d_out, int out_size) {
    const float* hs  = (const float*)d_in[0];
    const int*   tok = (const int*)d_in[1];
    const float* mu  = (const float*)d_in[2];
    const float* gup = (const float*)d_in[3];
    const float* dwn = (const float*)d_in[4];
    const float* rw  = (const float*)d_in[5];
    float* out = (float*)d_out;
    (void)in_sizes; (void)n_in; (void)out_size;

    cudaFuncSetAttribute(k_gemm1_mma, cudaFuncAttributeMaxDynamicSharedMemorySize,
                         SMEM_TOT);
    cudaFuncSetAttribute(k_gemm2_mma, cudaFuncAttributeMaxDynamicSharedMemorySize,
                         SMEM_TOT);

    k_init<<<1, 32>>>();
    k_router<<<N_TOK / 8, 256>>>(mu, tok, rw);
    k_plan_scatter<<<1, 256>>>();
    k_gather<<<N_TOK, 256>>>(hs);
    {
        __half *gh, *dh;
        cudaGetSymbolAddress((void**)&gh, g_gup_h);
        cudaGetSymbolAddress((void**)&dh, g_dwn_h);
        k_cvt<<<(E * H * F2 / 4 + 255) / 256, 256>>>(gup, gh, E * H * F2 / 4);
        k_cvt<<<(E * IE * H / 4 + 255) / 256, 256>>>(dwn, dh, E * IE * H / 4);
    }

    k_gemm1_mma<<<dim3(72, 8), 512, SMEM_TOT>>>();
    k_gemm2_mma<<<dim3(72, 8), 512, SMEM_TOT>>>(out);
}

// round 7
// speedup vs baseline: 2.3214x; 1.4977x over previous
#include <cuda_runtime.h>
#include <cuda_fp16.h>
#include <cstdint>

// ---------------- problem constants ----------------
#define N_TOK 8192
#define H     1024
#define E     8
#define IE    512
#define F2    1024
#define VOCAB 32000

// ---------------- scratch ----------------
__device__ int g_expert_ids[N_TOK];
__device__ int g_counts[E];
__device__ int g_offsets[E + 1];
__device__ int g_sorted[N_TOK];
__device__ int g_tile_expert[96];
__device__ int g_tile_mstart[96];
__device__ int g_num_tiles;

__device__ __half g_xs[(size_t)N_TOK * H];      // sorted order, fp16
__device__ __half g_gup_h[(size_t)E * H * F2];  // fp16 weights
__device__ __half g_dwn_h[(size_t)E * IE * H];
__device__ __half g_inter[(size_t)N_TOK * IE];  // sorted order, fp16

// ---------------- PTX helpers ----------------
__device__ __forceinline__ uint32_t s2u(const void* p) {
    uint32_t a;
    asm("{ .reg .u64 t; cvta.to.shared.u64 t, %1; cvt.u32.u64 %0, t; }"
        : "=r"(a) : "l"(p));
    return a;
}
__device__ __forceinline__ void cp16(uint32_t dst, const void* src) {
    asm volatile("cp.async.ca.shared.global [%0], [%1], 16;"
                 :: "r"(dst), "l"(src) : "memory");
}
__device__ __forceinline__ void cp_commit() {
    asm volatile("cp.async.commit_group;" ::: "memory");
}
__device__ __forceinline__ void cp_wait1() {
    asm volatile("cp.async.wait_group 1;" ::: "memory");
}
__device__ __forceinline__ void ldmx4(uint32_t* r, uint32_t a) {
    asm volatile("ldmatrix.sync.aligned.m8n8.x4.shared.b16 {%0,%1,%2,%3}, [%4];"
                 : "=r"(r[0]), "=r"(r[1]), "=r"(r[2]), "=r"(r[3]) : "r"(a));
}
__device__ __forceinline__ void ldmx4t(uint32_t* r, uint32_t a) {
    asm volatile("ldmatrix.sync.aligned.m8n8.x4.trans.shared.b16 {%0,%1,%2,%3}, [%4];"
                 : "=r"(r[0]), "=r"(r[1]), "=r"(r[2]), "=r"(r[3]) : "r"(a));
}
__device__ __forceinline__ void mma16816(float* d, const uint32_t* a,
                                         const uint32_t* b) {
    asm volatile(
        "mma.sync.aligned.m16n8k16.row.col.f32.f16.f16.f32 "
        "{%0,%1,%2,%3}, {%4,%5,%6,%7}, {%8,%9}, {%0,%1,%2,%3};"
        : "+f"(d[0]), "+f"(d[1]), "+f"(d[2]), "+f"(d[3])
        : "r"(a[0]), "r"(a[1]), "r"(a[2]), "r"(a[3]), "r"(b[0]), "r"(b[1]));
}

// ---------------- smem layout (BK = 32) ----------------
#define BK     32
#define A_ROWB 80    // 32 fp16 (64B) + 16B pad
#define B_ROWB 272   // 128 fp16 (256B) + 16B pad
#define OFF_AH 0
#define OFF_BH 10240
#define STG    18944
#define STAGE_BASE 512
#define SMEM_TOT (STAGE_BASE + 3 * STG)   // 57344

__device__ __forceinline__ uint32_t a_addr(uint32_t base, int lane, int mbase,
                                           int k16) {
    int row = mbase + (lane & 15);
    return base + row * A_ROWB + k16 * 32 + ((lane >> 4) << 4);
}
__device__ __forceinline__ uint32_t b_addr(uint32_t base, int lane, int nbase,
                                           int k16) {
    int krow = k16 * 16 + (lane & 15);
    return base + krow * B_ROWB + nbase * 2 + ((lane >> 4) << 4);
}

// warp tile 32x32: one k16 step = 4 ldmatrix.x4 + 8 HMMA
__device__ __forceinline__ void compute_k16(uint32_t stg, int lane, int warpM,
                                            int p0, int p1, int k16,
                                            float acc[2][4][4]) {
    uint32_t ah[2][4], bh[2][4];
#pragma unroll
    for (int i = 0; i < 2; i++)
        ldmx4(ah[i], a_addr(stg + OFF_AH, lane, warpM * 32 + i * 16, k16));
    ldmx4t(bh[0], b_addr(stg + OFF_BH, lane, p0, k16));
    ldmx4t(bh[1], b_addr(stg + OFF_BH, lane, p1, k16));
#pragma unroll
    for (int i = 0; i < 2; i++) {
#pragma unroll
        for (int j = 0; j < 4; j++)
            mma16816(acc[i][j], ah[i], &bh[j >> 1][(j & 1) * 2]);
    }
}

// ---------------- small kernels ----------------
__global__ void k_init() {
    if (threadIdx.x < E) g_counts[threadIdx.x] = 0;
}

__global__ void k_router(const float* __restrict__ mu, const int* __restrict__ tok,
                         const float* __restrict__ w) {
    __shared__ float ws[E * H];
    int tid = threadIdx.x;
    for (int i = tid; i < E * H; i += 256) ws[i] = w[i];
    __syncthreads();
    int warp = tid >> 5, lane = tid & 31;
    int n = blockIdx.x * 8 + warp;
    const float* mrow = mu + (size_t)n * H;
    float acc[E];
#pragma unroll
    for (int e = 0; e < E; e++) acc[e] = 0.f;
    for (int h = lane; h < H; h += 32) {
        float m = mrow[h];
#pragma unroll
        for (int e = 0; e < E; e++) acc[e] += m * ws[e * H + h];
    }
#pragma unroll
    for (int off = 16; off > 0; off >>= 1)
#pragma unroll
        for (int e = 0; e < E; e++)
            acc[e] += __shfl_down_sync(0xffffffffu, acc[e], off);
    if (lane == 0) {
        int id = tok[n];
        if (id < 0) id = 0;
        if (id >= VOCAB) id = VOCAB - 1;
        int base = id & (E - 1);
        float best = -1e30f;
        int be = 0;
#pragma unroll
        for (int e = 0; e < E; e++) {
            float v = acc[e] + (e == base ? 10.0f : 0.0f);
            if (v > best) { best = v; be = e; }
        }
        g_expert_ids[n] = be;
        atomicAdd(&g_counts[be], 1);
    }
}

__global__ void k_plan_scatter() {
    __shared__ int scur[E];
    if (threadIdx.x == 0) {
        int off = 0;
        for (int e = 0; e < E; e++) {
            g_offsets[e] = off;
            scur[e] = off;
            off += g_counts[e];
        }
        g_offsets[E] = off;
        int tt = 0;
        for (int e = 0; e < E; e++) {
            int cnt = g_counts[e];
            for (int ms = 0; ms < cnt; ms += 128) {
                g_tile_expert[tt] = e;
                g_tile_mstart[tt] = ms;
                tt++;
            }
        }
        g_num_tiles = tt;
    }
    __syncthreads();
    for (int n = threadIdx.x; n < N_TOK; n += 256) {
        int e = g_expert_ids[n];
        int p = atomicAdd(&scur[e], 1);
        g_sorted[p] = n;
    }
}

// gather x rows into sorted order + fp16 convert
__global__ void k_gather(const float* __restrict__ x) {
    int p = blockIdx.x;
    int token = g_sorted[p];
    int c = threadIdx.x * 4;
    float4 v = *(const float4*)(x + (size_t)token * H + c);
    __half2 a = __floats2half2_rn(v.x, v.y);
    __half2 b = __floats2half2_rn(v.z, v.w);
    ((uint2*)g_xs)[((size_t)p * H + c) >> 2] =
        make_uint2(*(uint32_t*)&a, *(uint32_t*)&b);
}

// fp32 -> fp16 convert (weights)
__global__ void k_cvt(const float* __restrict__ in, __half* __restrict__ out,
                      int n4) {
    int i = blockIdx.x * 256 + threadIdx.x;
    if (i >= n4) return;
    float4 v = ((const float4*)in)[i];
    __half2 a = __floats2half2_rn(v.x, v.y);
    __half2 b = __floats2half2_rn(v.z, v.w);
    ((uint2*)out)[i] = make_uint2(*(uint32_t*)&a, *(uint32_t*)&b);
}

// ---------------- GEMM1 stage load (512 threads, 2 cp16 each) --------------
__device__ __forceinline__ void g1_load(uint32_t sb, int s,
                                        const __half* wh,
                                        int m0, int k0, int n0g, int tid) {
    uint32_t stg = sb + s * STG;
    // A: row = tid>>2 (0..127), chunk c = tid&3 (16B of 64B row)
    int row = tid >> 2, c = tid & 3;
    int sr = m0 + row;
    if (sr > N_TOK - 1) sr = N_TOK - 1;
    cp16(stg + OFF_AH + row * A_ROWB + c * 16,
         g_xs + (size_t)sr * H + k0 + c * 8);
    // B: krow = tid>>4 (0..31), chunk c2 = tid&15 (16B of 256B row)
    int kr = tid >> 4, c2 = tid & 15;
    int col = (c2 < 8) ? (n0g + c2 * 8) : (IE + n0g + (c2 - 8) * 8);
    cp16(stg + OFF_BH + kr * B_ROWB + c2 * 16, wh + (size_t)(k0 + kr) * F2 + col);
}

__global__ __launch_bounds__(512) void k_gemm1_mma() {
    int t = blockIdx.x;
    if (t >= g_num_tiles) return;
    int e = g_tile_expert[t];
    int m0 = g_offsets[e] + g_tile_mstart[t];
    int rows = g_offsets[e + 1] - m0;
    if (rows > 128) rows = 128;
    int n0g = blockIdx.y * 64;

    extern __shared__ char smraw[];
    uint32_t sb = s2u(smraw) + STAGE_BASE;
    int tid = threadIdx.x;

    const __half* wh = g_gup_h + (size_t)e * H * F2;

    g1_load(sb, 0, wh, m0, 0, n0g, tid);
    cp_commit();
    g1_load(sb, 1, wh, m0, BK, n0g, tid);
    cp_commit();

    float acc[2][4][4];
#pragma unroll
    for (int i = 0; i < 2; i++)
#pragma unroll
        for (int j = 0; j < 4; j++)
#pragma unroll
            for (int r = 0; r < 4; r++) acc[i][j][r] = 0.f;

    int lane = tid & 31, w = tid >> 5;
    int warpM = w >> 2, warpN = w & 3;          // 4 x 4 warps
    int p0 = warpN * 16, p1 = 64 + warpN * 16;  // gate / up halves

    const int NS = H / BK;  // 32
    for (int ki = 0; ki < NS; ki++) {
        cp_wait1();
        __syncthreads();
        if (ki + 2 < NS) g1_load(sb, (ki + 2) % 3, wh, m0, (ki + 2) * BK, n0g, tid);
        cp_commit();
        uint32_t stg = sb + (ki % 3) * STG;
        compute_k16(stg, lane, warpM, p0, p1, 0, acc);
        compute_k16(stg, lane, warpM, p0, p1, 1, acc);
    }

    // epilogue: j=0,1 gate; j+2 up (same inter cols)
#pragma unroll
    for (int i = 0; i < 2; i++) {
        int r0 = warpM * 32 + i * 16 + (lane >> 2);
#pragma unroll
        for (int j = 0; j < 2; j++) {
            int col = n0g + warpN * 16 + j * 8 + (lane & 3) * 2;
#pragma unroll
            for (int hfa = 0; hfa < 2; hfa++) {
                int m = r0 + hfa * 8;
                if (m < rows) {
                    float g0 = acc[i][j][hfa * 2 + 0];
                    float g1 = acc[i][j][hfa * 2 + 1];
                    float u0 = acc[i][j + 2][hfa * 2 + 0];
                    float u1 = acc[i][j + 2][hfa * 2 + 1];
                    float v0 = g0 / (1.f + __expf(-g0)) * u0;
                    float v1 = g1 / (1.f + __expf(-g1)) * u1;
                    __half2 hv = __floats2half2_rn(v0, v1);
                    ((uint32_t*)g_inter)[((size_t)(m0 + m) * IE + col) >> 1] =
                        *(uint32_t*)&hv;
                }
            }
        }
    }
}

// ---------------- GEMM2 ----------------
__device__ __forceinline__ void g2_load(uint32_t sb, int s,
                                        const __half* wh,
                                        int m0, int k0, int n0, int tid) {
    uint32_t stg = sb + s * STG;
    int row = tid >> 2, c = tid & 3;
    int sr = m0 + row;
    if (sr > N_TOK - 1) sr = N_TOK - 1;
    cp16(stg + OFF_AH + row * A_ROWB + c * 16,
         g_inter + (size_t)sr * IE + k0 + c * 8);
    int kr = tid >> 4, c2 = tid & 15;
    cp16(stg + OFF_BH + kr * B_ROWB + c2 * 16,
         wh + (size_t)(k0 + kr) * H + n0 + c2 * 8);
}

__global__ __launch_bounds__(512) void k_gemm2_mma(float* __restrict__ out) {
    int t = blockIdx.x;
    if (t >= g_num_tiles) return;
    int e = g_tile_expert[t];
    int m0 = g_offsets[e] + g_tile_mstart[t];
    int rows = g_offsets[e + 1] - m0;
    if (rows > 128) rows = 128;
    int n0 = blockIdx.y * 128;

    extern __shared__ char smraw[];
    int* sRow = (int*)smraw;
    uint32_t sb = s2u(smraw) + STAGE_BASE;
    int tid = threadIdx.x;
    if (tid < 128) sRow[tid] = (tid < rows) ? g_sorted[m0 + tid] : -1;
    __syncthreads();

    const __half* wh = g_dwn_h + (size_t)e * IE * H;

    g2_load(sb, 0, wh, m0, 0, n0, tid);
    cp_commit();
    g2_load(sb, 1, wh, m0, BK, n0, tid);
    cp_commit();

    float acc[2][4][4];
#pragma unroll
    for (int i = 0; i < 2; i++)
#pragma unroll
        for (int j = 0; j < 4; j++)
#pragma unroll
            for (int r = 0; r < 4; r++) acc[i][j][r] = 0.f;

    int lane = tid & 31, w = tid >> 5;
    int warpM = w >> 2, warpN = w & 3;
    int p0 = warpN * 32, p1 = warpN * 32 + 16;

    const int NS = IE / BK;  // 16
    for (int ki = 0; ki < NS; ki++) {
        cp_wait1();
        __syncthreads();
        if (ki + 2 < NS) g2_load(sb, (ki + 2) % 3, wh, m0, (ki + 2) * BK, n0, tid);
        cp_commit();
        uint32_t stg = sb + (ki % 3) * STG;
        compute_k16(stg, lane, warpM, p0, p1, 0, acc);
        compute_k16(stg, lane, warpM, p0, p1, 1, acc);
    }

#pragma unroll
    for (int i = 0; i < 2; i++) {
        int r0 = warpM * 32 + i * 16 + (lane >> 2);
#pragma unroll
        for (int hfa = 0; hfa < 2; hfa++) {
            int m = r0 + hfa * 8;
            if (m < rows) {
                int token = sRow[m];
                float* po = out + (size_t)token * H + n0;
#pragma unroll
                for (int j = 0; j < 4; j++) {
                    int col = warpN * 32 + j * 8 + (lane & 3) * 2;
                    *(float2*)(po + col) =
                        make_float2(acc[i][j][hfa * 2 + 0], acc[i][j][hfa * 2 + 1]);
                }
            }
        }
    }
}

// ---------------- launch ----------------
extern "C" void kernel_launch(void* const* d_in, const int* in_sizes, int n_in,
                              void* d_out, int out_size) {
    const float* hs  = (const float*)d_in[0];
    const int*   tok = (const int*)d_in[1];
    const float* mu  = (const float*)d_in[2];
    const float* gup = (const float*)d_in[3];
    const float* dwn = (const float*)d_in[4];
    const float* rw  = (const float*)d_in[5];
    float* out = (float*)d_out;
    (void)in_sizes; (void)n_in; (void)out_size;

    cudaFuncSetAttribute(k_gemm1_mma, cudaFuncAttributeMaxDynamicSharedMemorySize,
                         SMEM_TOT);
    cudaFuncSetAttribute(k_gemm2_mma, cudaFuncAttributeMaxDynamicSharedMemorySize,
                         SMEM_TOT);

    k_init<<<1, 32>>>();
    k_router<<<N_TOK / 8, 256>>>(mu, tok, rw);
    k_plan_scatter<<<1, 256>>>();
    k_gather<<<N_TOK, 256>>>(hs);
    {
        __half *gh, *dh;
        cudaGetSymbolAddress((void**)&gh, g_gup_h);
        cudaGetSymbolAddress((void**)&dh, g_dwn_h);
        k_cvt<<<(E * H * F2 / 4 + 255) / 256, 256>>>(gup, gh, E * H * F2 / 4);
        k_cvt<<<(E * IE * H / 4 + 255) / 256, 256>>>(dwn, dh, E * IE * H / 4);
    }

    k_gemm1_mma<<<dim3(72, 8), 512, SMEM_TOT>>>();
    k_gemm2_mma<<<dim3(72, 8), 512, SMEM_TOT>>>(out);
}

// round 8
// speedup vs baseline: 2.5234x; 1.0870x over previous
#include <cuda_runtime.h>
#include <cuda_fp16.h>
#include <cstdint>

// ---------------- problem constants ----------------
#define N_TOK 8192
#define H     1024
#define E     8
#define IE    512
#define F2    1024
#define VOCAB 32000

// ---------------- scratch ----------------
__device__ int g_expert_ids[N_TOK];
__device__ int g_offsets[E + 1];
__device__ int g_sorted[N_TOK];
__device__ int g_tile_expert[96];
__device__ int g_tile_mstart[96];
__device__ int g_num_tiles;

__device__ __half g_xs[(size_t)N_TOK * H];      // sorted order, fp16
__device__ __half g_gup_h[(size_t)E * H * F2];  // fp16 weights
__device__ __half g_dwn_h[(size_t)E * IE * H];
__device__ __half g_inter[(size_t)N_TOK * IE];  // sorted order, fp16

// ---------------- PTX helpers ----------------
__device__ __forceinline__ uint32_t s2u(const void* p) {
    uint32_t a;
    asm("{ .reg .u64 t; cvta.to.shared.u64 t, %1; cvt.u32.u64 %0, t; }"
        : "=r"(a) : "l"(p));
    return a;
}
__device__ __forceinline__ void cp16(uint32_t dst, const void* src) {
    asm volatile("cp.async.ca.shared.global [%0], [%1], 16;"
                 :: "r"(dst), "l"(src) : "memory");
}
__device__ __forceinline__ void cp_commit() {
    asm volatile("cp.async.commit_group;" ::: "memory");
}
__device__ __forceinline__ void cp_wait1() {
    asm volatile("cp.async.wait_group 1;" ::: "memory");
}
__device__ __forceinline__ void ldmx4(uint32_t* r, uint32_t a) {
    asm volatile("ldmatrix.sync.aligned.m8n8.x4.shared.b16 {%0,%1,%2,%3}, [%4];"
                 : "=r"(r[0]), "=r"(r[1]), "=r"(r[2]), "=r"(r[3]) : "r"(a));
}
__device__ __forceinline__ void ldmx4t(uint32_t* r, uint32_t a) {
    asm volatile("ldmatrix.sync.aligned.m8n8.x4.trans.shared.b16 {%0,%1,%2,%3}, [%4];"
                 : "=r"(r[0]), "=r"(r[1]), "=r"(r[2]), "=r"(r[3]) : "r"(a));
}
__device__ __forceinline__ void mma16816(float* d, const uint32_t* a,
                                         const uint32_t* b) {
    asm volatile(
        "mma.sync.aligned.m16n8k16.row.col.f32.f16.f16.f32 "
        "{%0,%1,%2,%3}, {%4,%5,%6,%7}, {%8,%9}, {%0,%1,%2,%3};"
        : "+f"(d[0]), "+f"(d[1]), "+f"(d[2]), "+f"(d[3])
        : "r"(a[0]), "r"(a[1]), "r"(a[2]), "r"(a[3]), "r"(b[0]), "r"(b[1]));
}

// ---------------- smem layout (BK = 32) ----------------
#define BK     32
#define A_ROWB 80    // 32 fp16 (64B) + 16B pad
#define B_ROWB 272   // 128 fp16 (256B) + 16B pad
#define OFF_AH 0
#define OFF_BH 10240
#define STG    18944
#define STAGE_BASE 512
#define SMEM_TOT (STAGE_BASE + 3 * STG)   // 57344

__device__ __forceinline__ uint32_t a_addr(uint32_t base, int lane, int mbase,
                                           int k16) {
    int row = mbase + (lane & 15);
    return base + row * A_ROWB + k16 * 32 + ((lane >> 4) << 4);
}
__device__ __forceinline__ uint32_t b_addr(uint32_t base, int lane, int nbase,
                                           int k16) {
    int krow = k16 * 16 + (lane & 15);
    return base + krow * B_ROWB + nbase * 2 + ((lane >> 4) << 4);
}

// warp tile 64x32: one k16 step = 6 ldmatrix.x4 + 16 HMMA
__device__ __forceinline__ void compute_k16(uint32_t stg, int lane, int warpM,
                                            int p0, int p1, int k16,
                                            float acc[4][4][4]) {
    uint32_t ah[4][4], bh[2][4];
#pragma unroll
    for (int i = 0; i < 4; i++)
        ldmx4(ah[i], a_addr(stg + OFF_AH, lane, warpM * 64 + i * 16, k16));
    ldmx4t(bh[0], b_addr(stg + OFF_BH, lane, p0, k16));
    ldmx4t(bh[1], b_addr(stg + OFF_BH, lane, p1, k16));
#pragma unroll
    for (int i = 0; i < 4; i++) {
#pragma unroll
        for (int j = 0; j < 4; j++)
            mma16816(acc[i][j], ah[i], &bh[j >> 1][(j & 1) * 2]);
    }
}

// ---------------- small kernels ----------------
__global__ void k_router(const float* __restrict__ mu, const int* __restrict__ tok,
                         const float* __restrict__ w) {
    __shared__ float ws[E * H];
    int tid = threadIdx.x;
    for (int i = tid; i < E * H; i += 256) ws[i] = w[i];
    __syncthreads();
    int warp = tid >> 5, lane = tid & 31;
    int n = blockIdx.x * 8 + warp;
    const float* mrow = mu + (size_t)n * H;
    float acc[E];
#pragma unroll
    for (int e = 0; e < E; e++) acc[e] = 0.f;
    for (int h = lane; h < H; h += 32) {
        float m = mrow[h];
#pragma unroll
        for (int e = 0; e < E; e++) acc[e] += m * ws[e * H + h];
    }
#pragma unroll
    for (int off = 16; off > 0; off >>= 1)
#pragma unroll
        for (int e = 0; e < E; e++)
            acc[e] += __shfl_down_sync(0xffffffffu, acc[e], off);
    if (lane == 0) {
        int id = tok[n];
        if (id < 0) id = 0;
        if (id >= VOCAB) id = VOCAB - 1;
        int base = id & (E - 1);
        float best = -1e30f;
        int be = 0;
#pragma unroll
        for (int e = 0; e < E; e++) {
            float v = acc[e] + (e == base ? 10.0f : 0.0f);
            if (v > best) { best = v; be = e; }
        }
        g_expert_ids[n] = be;
    }
}

// histogram + prefix + tile table + scatter, single block
__global__ void k_plan_scatter() {
    __shared__ int scnt[E];
    __shared__ int scur[E];
    int tid = threadIdx.x;
    if (tid < E) scnt[tid] = 0;
    __syncthreads();
    for (int n = tid; n < N_TOK; n += 256)
        atomicAdd(&scnt[g_expert_ids[n]], 1);
    __syncthreads();
    if (tid == 0) {
        int off = 0;
        for (int e = 0; e < E; e++) {
            g_offsets[e] = off;
            scur[e] = off;
            off += scnt[e];
        }
        g_offsets[E] = off;
        int tt = 0;
        for (int e = 0; e < E; e++) {
            for (int ms = 0; ms < scnt[e]; ms += 128) {
                g_tile_expert[tt] = e;
                g_tile_mstart[tt] = ms;
                tt++;
            }
        }
        g_num_tiles = tt;
    }
    __syncthreads();
    for (int n = tid; n < N_TOK; n += 256) {
        int e = g_expert_ids[n];
        int p = atomicAdd(&scur[e], 1);
        g_sorted[p] = n;
    }
}

// gather x rows into sorted order + fp16 convert
__global__ void k_gather(const float* __restrict__ x) {
    int p = blockIdx.x;
    int token = g_sorted[p];
    int c = threadIdx.x * 4;
    float4 v = *(const float4*)(x + (size_t)token * H + c);
    __half2 a = __floats2half2_rn(v.x, v.y);
    __half2 b = __floats2half2_rn(v.z, v.w);
    ((uint2*)g_xs)[((size_t)p * H + c) >> 2] =
        make_uint2(*(uint32_t*)&a, *(uint32_t*)&b);
}

// fp32 -> fp16 convert: both weight tensors in one launch
#define GUP4 (E * H * F2 / 4)   // 2097152
#define DWN4 (E * IE * H / 4)   // 1048576
__global__ void k_cvt2(const float* __restrict__ gup,
                       const float* __restrict__ dwn) {
    int i = blockIdx.x * 256 + threadIdx.x;
    const float* in;
    __half* out;
    int idx;
    if (i < GUP4) { in = gup; out = g_gup_h; idx = i; }
    else if (i < GUP4 + DWN4) { in = dwn; out = g_dwn_h; idx = i - GUP4; }
    else return;
    float4 v = ((const float4*)in)[idx];
    __half2 a = __floats2half2_rn(v.x, v.y);
    __half2 b = __floats2half2_rn(v.z, v.w);
    ((uint2*)out)[idx] = make_uint2(*(uint32_t*)&a, *(uint32_t*)&b);
}

// ---------------- GEMM1 stage load (256 threads, 4 cp16 each) --------------
__device__ __forceinline__ void g1_load(uint32_t sb, int s,
                                        const __half* wh,
                                        int m0, int k0, int n0g, int tid) {
    uint32_t stg = sb + s * STG;
#pragma unroll
    for (int q = 0; q < 2; q++) {
        int t = tid * 2 + q;  // 0..511
        // A: row = t>>2 (0..127), chunk c = t&3 (16B of 64B row)
        int row = t >> 2, c = t & 3;
        int sr = m0 + row;
        if (sr > N_TOK - 1) sr = N_TOK - 1;
        cp16(stg + OFF_AH + row * A_ROWB + c * 16,
             g_xs + (size_t)sr * H + k0 + c * 8);
        // B: krow = t>>4 (0..31), chunk c2 = t&15 (16B of 256B row)
        int kr = t >> 4, c2 = t & 15;
        int col = (c2 < 8) ? (n0g + c2 * 8) : (IE + n0g + (c2 - 8) * 8);
        cp16(stg + OFF_BH + kr * B_ROWB + c2 * 16,
             wh + (size_t)(k0 + kr) * F2 + col);
    }
}

__global__ __launch_bounds__(256, 2) void k_gemm1_mma() {
    int t = blockIdx.x;
    if (t >= g_num_tiles) return;
    int e = g_tile_expert[t];
    int m0 = g_offsets[e] + g_tile_mstart[t];
    int rows = g_offsets[e + 1] - m0;
    if (rows > 128) rows = 128;
    int n0g = blockIdx.y * 64;

    extern __shared__ char smraw[];
    uint32_t sb = s2u(smraw) + STAGE_BASE;
    int tid = threadIdx.x;

    const __half* wh = g_gup_h + (size_t)e * H * F2;

    g1_load(sb, 0, wh, m0, 0, n0g, tid);
    cp_commit();
    g1_load(sb, 1, wh, m0, BK, n0g, tid);
    cp_commit();

    float acc[4][4][4];
#pragma unroll
    for (int i = 0; i < 4; i++)
#pragma unroll
        for (int j = 0; j < 4; j++)
#pragma unroll
            for (int r = 0; r < 4; r++) acc[i][j][r] = 0.f;

    int lane = tid & 31, w = tid >> 5;
    int warpM = w >> 2, warpN = w & 3;          // 2M x 4N
    int p0 = warpN * 16, p1 = 64 + warpN * 16;  // gate / up halves

    const int NS = H / BK;  // 32
    for (int ki = 0; ki < NS; ki++) {
        cp_wait1();
        __syncthreads();
        if (ki + 2 < NS) g1_load(sb, (ki + 2) % 3, wh, m0, (ki + 2) * BK, n0g, tid);
        cp_commit();
        uint32_t stg = sb + (ki % 3) * STG;
        compute_k16(stg, lane, warpM, p0, p1, 0, acc);
        compute_k16(stg, lane, warpM, p0, p1, 1, acc);
    }

    // epilogue: j=0,1 gate; j+2 up (same inter cols)
#pragma unroll
    for (int i = 0; i < 4; i++) {
        int r0 = warpM * 64 + i * 16 + (lane >> 2);
#pragma unroll
        for (int j = 0; j < 2; j++) {
            int col = n0g + warpN * 16 + j * 8 + (lane & 3) * 2;
#pragma unroll
            for (int hfa = 0; hfa < 2; hfa++) {
                int m = r0 + hfa * 8;
                if (m < rows) {
                    float g0 = acc[i][j][hfa * 2 + 0];
                    float g1 = acc[i][j][hfa * 2 + 1];
                    float u0 = acc[i][j + 2][hfa * 2 + 0];
                    float u1 = acc[i][j + 2][hfa * 2 + 1];
                    float v0 = g0 / (1.f + __expf(-g0)) * u0;
                    float v1 = g1 / (1.f + __expf(-g1)) * u1;
                    __half2 hv = __floats2half2_rn(v0, v1);
                    ((uint32_t*)g_inter)[((size_t)(m0 + m) * IE + col) >> 1] =
                        *(uint32_t*)&hv;
                }
            }
        }
    }
}

// ---------------- GEMM2 ----------------
__device__ __forceinline__ void g2_load(uint32_t sb, int s,
                                        const __half* wh,
                                        int m0, int k0, int n0, int tid) {
    uint32_t stg = sb + s * STG;
#pragma unroll
    for (int q = 0; q < 2; q++) {
        int t = tid * 2 + q;
        int row = t >> 2, c = t & 3;
        int sr = m0 + row;
        if (sr > N_TOK - 1) sr = N_TOK - 1;
        cp16(stg + OFF_AH + row * A_ROWB + c * 16,
             g_inter + (size_t)sr * IE + k0 + c * 8);
        int kr = t >> 4, c2 = t & 15;
        cp16(stg + OFF_BH + kr * B_ROWB + c2 * 16,
             wh + (size_t)(k0 + kr) * H + n0 + c2 * 8);
    }
}

__global__ __launch_bounds__(256, 2) void k_gemm2_mma(float* __restrict__ out) {
    int t = blockIdx.x;
    if (t >= g_num_tiles) return;
    int e = g_tile_expert[t];
    int m0 = g_offsets[e] + g_tile_mstart[t];
    int rows = g_offsets[e + 1] - m0;
    if (rows > 128) rows = 128;
    int n0 = blockIdx.y * 128;

    extern __shared__ char smraw[];
    int* sRow = (int*)smraw;
    uint32_t sb = s2u(smraw) + STAGE_BASE;
    int tid = threadIdx.x;
    if (tid < 128) sRow[tid] = (tid < rows) ? g_sorted[m0 + tid] : -1;
    __syncthreads();

    const __half* wh = g_dwn_h + (size_t)e * IE * H;

    g2_load(sb, 0, wh, m0, 0, n0, tid);
    cp_commit();
    g2_load(sb, 1, wh, m0, BK, n0, tid);
    cp_commit();

    float acc[4][4][4];
#pragma unroll
    for (int i = 0; i < 4; i++)
#pragma unroll
        for (int j = 0; j < 4; j++)
#pragma unroll
            for (int r = 0; r < 4; r++) acc[i][j][r] = 0.f;

    int lane = tid & 31, w = tid >> 5;
    int warpM = w >> 2, warpN = w & 3;
    int p0 = warpN * 32, p1 = warpN * 32 + 16;

    const int NS = IE / BK;  // 16
    for (int ki = 0; ki < NS; ki++) {
        cp_wait1();
        __syncthreads();
        if (ki + 2 < NS) g2_load(sb, (ki + 2) % 3, wh, m0, (ki + 2) * BK, n0, tid);
        cp_commit();
        uint32_t stg = sb + (ki % 3) * STG;
        compute_k16(stg, lane, warpM, p0, p1, 0, acc);
        compute_k16(stg, lane, warpM, p0, p1, 1, acc);
    }

#pragma unroll
    for (int i = 0; i < 4; i++) {
        int r0 = warpM * 64 + i * 16 + (lane >> 2);
#pragma unroll
        for (int hfa = 0; hfa < 2; hfa++) {
            int m = r0 + hfa * 8;
            if (m < rows) {
                int token = sRow[m];
                float* po = out + (size_t)token * H + n0;
#pragma unroll
                for (int j = 0; j < 4; j++) {
                    int col = warpN * 32 + j * 8 + (lane & 3) * 2;
                    *(float2*)(po + col) =
                        make_float2(acc[i][j][hfa * 2 + 0], acc[i][j][hfa * 2 + 1]);
                }
            }
        }
    }
}

// ---------------- launch ----------------
extern "C" void kernel_launch(void* const* d_in, const int* in_sizes, int n_in,
                              void* d_out, int out_size) {
    const float* hs  = (const float*)d_in[0];
    const int*   tok = (const int*)d_in[1];
    const float* mu  = (const float*)d_in[2];
    const float* gup = (const float*)d_in[3];
    const float* dwn = (const float*)d_in[4];
    const float* rw  = (const float*)d_in[5];
    float* out = (float*)d_out;
    (void)in_sizes; (void)n_in; (void)out_size;

    cudaFuncSetAttribute(k_gemm1_mma, cudaFuncAttributeMaxDynamicSharedMemorySize,
                         SMEM_TOT);
    cudaFuncSetAttribute(k_gemm2_mma, cudaFuncAttributeMaxDynamicSharedMemorySize,
                         SMEM_TOT);

    k_router<<<N_TOK / 8, 256>>>(mu, tok, rw);
    k_plan_scatter<<<1, 256>>>();
    k_gather<<<N_TOK, 256>>>(hs);
    k_cvt2<<<(GUP4 + DWN4 + 255) / 256, 256>>>(gup, dwn);

    k_gemm1_mma<<<dim3(72, 8), 256, SMEM_TOT>>>();
    k_gemm2_mma<<<dim3(72, 8), 256, SMEM_TOT>>>(out);
}

// round 9
// speedup vs baseline: 2.6111x; 1.0347x over previous
#include <cuda_runtime.h>
#include <cuda_fp16.h>
#include <cstdint>

// ---------------- problem constants ----------------
#define N_TOK 8192
#define H     1024
#define E     8
#define IE    512
#define F2    1024
#define VOCAB 32000

// ---------------- scratch ----------------
__device__ int g_expert_ids[N_TOK];
__device__ int g_counts[E];          // zero-initialized; k_plan re-zeros after use
__device__ int g_cursor[E];
__device__ int g_offsets[E + 1];
__device__ int g_sorted[N_TOK];
__device__ int g_tile_expert[96];
__device__ int g_tile_mstart[96];
__device__ int g_num_tiles;

__device__ __half g_xs[(size_t)N_TOK * H];      // sorted order, fp16
__device__ __half g_gup_h[(size_t)E * H * F2];  // fp16 weights
__device__ __half g_dwn_h[(size_t)E * IE * H];
__device__ __half g_inter[(size_t)N_TOK * IE];  // sorted order, fp16

// ---------------- PTX helpers ----------------
__device__ __forceinline__ uint32_t s2u(const void* p) {
    uint32_t a;
    asm("{ .reg .u64 t; cvta.to.shared.u64 t, %1; cvt.u32.u64 %0, t; }"
        : "=r"(a) : "l"(p));
    return a;
}
__device__ __forceinline__ void cp16(uint32_t dst, const void* src) {
    asm volatile("cp.async.ca.shared.global [%0], [%1], 16;"
                 :: "r"(dst), "l"(src) : "memory");
}
__device__ __forceinline__ void cp_commit() {
    asm volatile("cp.async.commit_group;" ::: "memory");
}
__device__ __forceinline__ void cp_wait1() {
    asm volatile("cp.async.wait_group 1;" ::: "memory");
}
__device__ __forceinline__ void ldmx4(uint32_t* r, uint32_t a) {
    asm volatile("ldmatrix.sync.aligned.m8n8.x4.shared.b16 {%0,%1,%2,%3}, [%4];"
                 : "=r"(r[0]), "=r"(r[1]), "=r"(r[2]), "=r"(r[3]) : "r"(a));
}
__device__ __forceinline__ void ldmx4t(uint32_t* r, uint32_t a) {
    asm volatile("ldmatrix.sync.aligned.m8n8.x4.trans.shared.b16 {%0,%1,%2,%3}, [%4];"
                 : "=r"(r[0]), "=r"(r[1]), "=r"(r[2]), "=r"(r[3]) : "r"(a));
}
__device__ __forceinline__ void mma16816(float* d, const uint32_t* a,
                                         const uint32_t* b) {
    asm volatile(
        "mma.sync.aligned.m16n8k16.row.col.f32.f16.f16.f32 "
        "{%0,%1,%2,%3}, {%4,%5,%6,%7}, {%8,%9}, {%0,%1,%2,%3};"
        : "+f"(d[0]), "+f"(d[1]), "+f"(d[2]), "+f"(d[3])
        : "r"(a[0]), "r"(a[1]), "r"(a[2]), "r"(a[3]), "r"(b[0]), "r"(b[1]));
}

// ---------------- smem layout (BK = 64) ----------------
#define BK     64
#define A_ROWB 144   // 64 fp16 (128B) + 16B pad
#define B_ROWB 272   // 128 fp16 (256B) + 16B pad
#define OFF_AH 0
#define OFF_BH 18432
#define STG    35840          // 18432 + 64*272
#define STAGE_BASE 512
#define SMEM_TOT (STAGE_BASE + 3 * STG)   // 108032 (x2 CTA = 216064 <= 228KB)

__device__ __forceinline__ uint32_t a_addr(uint32_t base, int lane, int mbase,
                                           int k16) {
    int row = mbase + (lane & 15);
    return base + row * A_ROWB + k16 * 32 + ((lane >> 4) << 4);
}
__device__ __forceinline__ uint32_t b_addr(uint32_t base, int lane, int nbase,
                                           int k16) {
    int krow = k16 * 16 + (lane & 15);
    return base + krow * B_ROWB + nbase * 2 + ((lane >> 4) << 4);
}

// warp tile 64x32: one k16 step = 6 ldmatrix.x4 + 16 HMMA
__device__ __forceinline__ void compute_k16(uint32_t stg, int lane, int warpM,
                                            int p0, int p1, int k16,
                                            float acc[4][4][4]) {
    uint32_t ah[4][4], bh[2][4];
#pragma unroll
    for (int i = 0; i < 4; i++)
        ldmx4(ah[i], a_addr(stg + OFF_AH, lane, warpM * 64 + i * 16, k16));
    ldmx4t(bh[0], b_addr(stg + OFF_BH, lane, p0, k16));
    ldmx4t(bh[1], b_addr(stg + OFF_BH, lane, p1, k16));
#pragma unroll
    for (int i = 0; i < 4; i++) {
#pragma unroll
        for (int j = 0; j < 4; j++)
            mma16816(acc[i][j], ah[i], &bh[j >> 1][(j & 1) * 2]);
    }
}

// ---------------- router (+ histogram) ----------------
__global__ void k_router(const float* __restrict__ mu, const int* __restrict__ tok,
                         const float* __restrict__ w) {
    __shared__ float ws[E * H];
    __shared__ int hist[E];
    int tid = threadIdx.x;
    if (tid < E) hist[tid] = 0;
    for (int i = tid; i < E * H; i += 256) ws[i] = w[i];
    __syncthreads();
    int warp = tid >> 5, lane = tid & 31;
    int n = blockIdx.x * 8 + warp;
    const float* mrow = mu + (size_t)n * H;
    float acc[E];
#pragma unroll
    for (int e = 0; e < E; e++) acc[e] = 0.f;
    for (int h = lane; h < H; h += 32) {
        float m = mrow[h];
#pragma unroll
        for (int e = 0; e < E; e++) acc[e] += m * ws[e * H + h];
    }
#pragma unroll
    for (int off = 16; off > 0; off >>= 1)
#pragma unroll
        for (int e = 0; e < E; e++)
            acc[e] += __shfl_down_sync(0xffffffffu, acc[e], off);
    if (lane == 0) {
        int id = tok[n];
        if (id < 0) id = 0;
        if (id >= VOCAB) id = VOCAB - 1;
        int base = id & (E - 1);
        float best = -1e30f;
        int be = 0;
#pragma unroll
        for (int e = 0; e < E; e++) {
            float v = acc[e] + (e == base ? 10.0f : 0.0f);
            if (v > best) { best = v; be = e; }
        }
        g_expert_ids[n] = be;
        atomicAdd(&hist[be], 1);
    }
    __syncthreads();
    if (tid < E && hist[tid] > 0) atomicAdd(&g_counts[tid], hist[tid]);
}

// prefix + tile table; re-zeros g_counts so next graph replay starts clean
__global__ void k_plan() {
    if (threadIdx.x == 0) {
        int off = 0;
        for (int e = 0; e < E; e++) {
            g_offsets[e] = off;
            g_cursor[e] = off;
            off += g_counts[e];
        }
        g_offsets[E] = off;
        int tt = 0;
        for (int e = 0; e < E; e++) {
            int cnt = g_counts[e];
            for (int ms = 0; ms < cnt; ms += 128) {
                g_tile_expert[tt] = e;
                g_tile_mstart[tt] = ms;
                tt++;
            }
        }
        g_num_tiles = tt;
        for (int e = 0; e < E; e++) g_counts[e] = 0;
    }
}

// fused scatter + gather + fp16 convert: block = one token
__global__ void k_sg(const float* __restrict__ x) {
    __shared__ int sp;
    int n = blockIdx.x;
    if (threadIdx.x == 0) {
        int e = g_expert_ids[n];
        int p = atomicAdd(&g_cursor[e], 1);
        g_sorted[p] = n;
        sp = p;
    }
    __syncthreads();
    int p = sp;
    int c = threadIdx.x * 4;
    float4 v = *(const float4*)(x + (size_t)n * H + c);
    __half2 a = __floats2half2_rn(v.x, v.y);
    __half2 b = __floats2half2_rn(v.z, v.w);
    ((uint2*)g_xs)[((size_t)p * H + c) >> 2] =
        make_uint2(*(uint32_t*)&a, *(uint32_t*)&b);
}

// fp32 -> fp16 convert: both weight tensors in one launch
#define GUP4 (E * H * F2 / 4)   // 2097152
#define DWN4 (E * IE * H / 4)   // 1048576
__global__ void k_cvt2(const float* __restrict__ gup,
                       const float* __restrict__ dwn) {
    int i = blockIdx.x * 256 + threadIdx.x;
    const float* in;
    __half* out;
    int idx;
    if (i < GUP4) { in = gup; out = g_gup_h; idx = i; }
    else if (i < GUP4 + DWN4) { in = dwn; out = g_dwn_h; idx = i - GUP4; }
    else return;
    float4 v = ((const float4*)in)[idx];
    __half2 a = __floats2half2_rn(v.x, v.y);
    __half2 b = __floats2half2_rn(v.z, v.w);
    ((uint2*)out)[idx] = make_uint2(*(uint32_t*)&a, *(uint32_t*)&b);
}

// ---------------- GEMM1 stage load (256 threads, 8 cp16 each) --------------
__device__ __forceinline__ void g1_load(uint32_t sb, int s,
                                        const __half* wh,
                                        int m0, int k0, int n0g, int tid) {
    uint32_t stg = sb + s * STG;
#pragma unroll
    for (int q = 0; q < 4; q++) {
        int t = tid + q * 256;  // 0..1023
        // A: row = t>>3 (0..127), chunk c = t&7 (16B of 128B row)
        int row = t >> 3, c = t & 7;
        int sr = m0 + row;
        if (sr > N_TOK - 1) sr = N_TOK - 1;
        cp16(stg + OFF_AH + row * A_ROWB + c * 16,
             g_xs + (size_t)sr * H + k0 + c * 8);
        // B: krow = t>>4 (0..63), chunk c2 = t&15 (16B of 256B row)
        int kr = t >> 4, c2 = t & 15;
        int col = (c2 < 8) ? (n0g + c2 * 8) : (IE + n0g + (c2 - 8) * 8);
        cp16(stg + OFF_BH + kr * B_ROWB + c2 * 16,
             wh + (size_t)(k0 + kr) * F2 + col);
    }
}

__global__ __launch_bounds__(256, 2) void k_gemm1_mma() {
    int t = blockIdx.x;
    if (t >= g_num_tiles) return;
    int e = g_tile_expert[t];
    int m0 = g_offsets[e] + g_tile_mstart[t];
    int rows = g_offsets[e + 1] - m0;
    if (rows > 128) rows = 128;
    int n0g = blockIdx.y * 64;

    extern __shared__ char smraw[];
    uint32_t sb = s2u(smraw) + STAGE_BASE;
    int tid = threadIdx.x;

    const __half* wh = g_gup_h + (size_t)e * H * F2;

    g1_load(sb, 0, wh, m0, 0, n0g, tid);
    cp_commit();
    g1_load(sb, 1, wh, m0, BK, n0g, tid);
    cp_commit();

    float acc[4][4][4];
#pragma unroll
    for (int i = 0; i < 4; i++)
#pragma unroll
        for (int j = 0; j < 4; j++)
#pragma unroll
            for (int r = 0; r < 4; r++) acc[i][j][r] = 0.f;

    int lane = tid & 31, w = tid >> 5;
    int warpM = w >> 2, warpN = w & 3;          // 2M x 4N
    int p0 = warpN * 16, p1 = 64 + warpN * 16;  // gate / up halves

    const int NS = H / BK;  // 16
    for (int ki = 0; ki < NS; ki++) {
        cp_wait1();
        __syncthreads();
        if (ki + 2 < NS) g1_load(sb, (ki + 2) % 3, wh, m0, (ki + 2) * BK, n0g, tid);
        cp_commit();
        uint32_t stg = sb + (ki % 3) * STG;
#pragma unroll
        for (int k16 = 0; k16 < 4; k16++)
            compute_k16(stg, lane, warpM, p0, p1, k16, acc);
    }

    // epilogue: j=0,1 gate; j+2 up (same inter cols)
#pragma unroll
    for (int i = 0; i < 4; i++) {
        int r0 = warpM * 64 + i * 16 + (lane >> 2);
#pragma unroll
        for (int j = 0; j < 2; j++) {
            int col = n0g + warpN * 16 + j * 8 + (lane & 3) * 2;
#pragma unroll
            for (int hfa = 0; hfa < 2; hfa++) {
                int m = r0 + hfa * 8;
                if (m < rows) {
                    float g0 = acc[i][j][hfa * 2 + 0];
                    float g1 = acc[i][j][hfa * 2 + 1];
                    float u0 = acc[i][j + 2][hfa * 2 + 0];
                    float u1 = acc[i][j + 2][hfa * 2 + 1];
                    float v0 = g0 / (1.f + __expf(-g0)) * u0;
                    float v1 = g1 / (1.f + __expf(-g1)) * u1;
                    __half2 hv = __floats2half2_rn(v0, v1);
                    ((uint32_t*)g_inter)[((size_t)(m0 + m) * IE + col) >> 1] =
                        *(uint32_t*)&hv;
                }
            }
        }
    }
}

// ---------------- GEMM2 ----------------
__device__ __forceinline__ void g2_load(uint32_t sb, int s,
                                        const __half* wh,
                                        int m0, int k0, int n0, int tid) {
    uint32_t stg = sb + s * STG;
#pragma unroll
    for (int q = 0; q < 4; q++) {
        int t = tid + q * 256;
        int row = t >> 3, c = t & 7;
        int sr = m0 + row;
        if (sr > N_TOK - 1) sr = N_TOK - 1;
        cp16(stg + OFF_AH + row * A_ROWB + c * 16,
             g_inter + (size_t)sr * IE + k0 + c * 8);
        int kr = t >> 4, c2 = t & 15;
        cp16(stg + OFF_BH + kr * B_ROWB + c2 * 16,
             wh + (size_t)(k0 + kr) * H + n0 + c2 * 8);
    }
}

__global__ __launch_bounds__(256, 2) void k_gemm2_mma(float* __restrict__ out) {
    int t = blockIdx.x;
    if (t >= g_num_tiles) return;
    int e = g_tile_expert[t];
    int m0 = g_offsets[e] + g_tile_mstart[t];
    int rows = g_offsets[e + 1] - m0;
    if (rows > 128) rows = 128;
    int n0 = blockIdx.y * 128;

    extern __shared__ char smraw[];
    int* sRow = (int*)smraw;
    uint32_t sb = s2u(smraw) + STAGE_BASE;
    int tid = threadIdx.x;
    if (tid < 128) sRow[tid] = (tid < rows) ? g_sorted[m0 + tid] : -1;
    __syncthreads();

    const __half* wh = g_dwn_h + (size_t)e * IE * H;

    g2_load(sb, 0, wh, m0, 0, n0, tid);
    cp_commit();
    g2_load(sb, 1, wh, m0, BK, n0, tid);
    cp_commit();

    float acc[4][4][4];
#pragma unroll
    for (int i = 0; i < 4; i++)
#pragma unroll
        for (int j = 0; j < 4; j++)
#pragma unroll
            for (int r = 0; r < 4; r++) acc[i][j][r] = 0.f;

    int lane = tid & 31, w = tid >> 5;
    int warpM = w >> 2, warpN = w & 3;
    int p0 = warpN * 32, p1 = warpN * 32 + 16;

    const int NS = IE / BK;  // 8
    for (int ki = 0; ki < NS; ki++) {
        cp_wait1();
        __syncthreads();
        if (ki + 2 < NS) g2_load(sb, (ki + 2) % 3, wh, m0, (ki + 2) * BK, n0, tid);
        cp_commit();
        uint32_t stg = sb + (ki % 3) * STG;
#pragma unroll
        for (int k16 = 0; k16 < 4; k16++)
            compute_k16(stg, lane, warpM, p0, p1, k16, acc);
    }

#pragma unroll
    for (int i = 0; i < 4; i++) {
        int r0 = warpM * 64 + i * 16 + (lane >> 2);
#pragma unroll
        for (int hfa = 0; hfa < 2; hfa++) {
            int m = r0 + hfa * 8;
            if (m < rows) {
                int token = sRow[m];
                float* po = out + (size_t)token * H + n0;
#pragma unroll
                for (int j = 0; j < 4; j++) {
                    int col = warpN * 32 + j * 8 + (lane & 3) * 2;
                    *(float2*)(po + col) =
                        make_float2(acc[i][j][hfa * 2 + 0], acc[i][j][hfa * 2 + 1]);
                }
            }
        }
    }
}

// ---------------- launch ----------------
extern "C" void kernel_launch(void* const* d_in, const int* in_sizes, int n_in,
                              void* d_out, int out_size) {
    const float* hs  = (const float*)d_in[0];
    const int*   tok = (const int*)d_in[1];
    const float* mu  = (const float*)d_in[2];
    const float* gup = (const float*)d_in[3];
    const float* dwn = (const float*)d_in[4];
    const float* rw  = (const float*)d_in[5];
    float* out = (float*)d_out;
    (void)in_sizes; (void)n_in; (void)out_size;

    cudaFuncSetAttribute(k_gemm1_mma, cudaFuncAttributeMaxDynamicSharedMemorySize,
                         SMEM_TOT);
    cudaFuncSetAttribute(k_gemm2_mma, cudaFuncAttributeMaxDynamicSharedMemorySize,
                         SMEM_TOT);

    k_router<<<N_TOK / 8, 256>>>(mu, tok, rw);
    k_plan<<<1, 32>>>();
    k_sg<<<N_TOK, 256>>>(hs);
    k_cvt2<<<(GUP4 + DWN4 + 255) / 256, 256>>>(gup, dwn);

    k_gemm1_mma<<<dim3(72, 8), 256, SMEM_TOT>>>();
    k_gemm2_mma<<<dim3(72, 8), 256, SMEM_TOT>>>(out);
}